// round 1
// baseline (speedup 1.0000x reference)
#include <cuda_runtime.h>
#include <math.h>

#define B_      4
#define N_      32768
#define C_      256
#define H_      8
#define D_      64
#define G_      64
#define INNER_  512
#define BNTOK   (B_*N_)          // 131072

// ---------------- scratch (device globals; allocation-free) ----------------
__device__ float g_mid[(size_t)BNTOK * 1024];   // [m][0:512]=fx, [512:1024]=xm
__device__ float g_w  [(size_t)BNTOK * 512];    // slice weights [m][h*64+g]
__device__ float g_st [B_*H_*G_*D_];            // pooled slice tokens (pre-norm)
__device__ float g_nrm[B_*H_*G_];               // softmax-weight sums
__device__ float g_os [B_*H_*G_*D_];            // attention output per slice
__device__ float g_P  [B_*INNER_*C_];           // P[b][h*64+g][c]

// ---------------- K0: zero accumulators ----------------
__global__ void k_zero() {
    int i = blockIdx.x * blockDim.x + threadIdx.x;
    if (i < B_*H_*G_*D_) g_st[i] = 0.f;
    if (i < B_*H_*G_)    g_nrm[i] = 0.f;
}

// ---------------- generic fp32 GEMM (two modes) ----------------
// mode 0: C[m][1024] = x[m][256] @ [W_fx | W_x] + bias   -> g_mid
// mode 1: out[m][256] = g_w[m][512] @ P[b][512][256] + b_out -> d_out
#define BM 64
#define BN 128
#define BK 16

__global__ void __launch_bounds__(256) k_gemm(
    int mode,
    const float* __restrict__ Aparam, int lda, int Ktot,
    const float* __restrict__ Wfx, const float* __restrict__ Wx,
    const float* __restrict__ bfx, const float* __restrict__ bx,
    const float* __restrict__ bout,
    float* __restrict__ OutParam)
{
    __shared__ float As[BK][BM + 4];
    __shared__ float Bs[BK][BN];

    const int m0 = blockIdx.y * BM;
    const int n0 = blockIdx.x * BN;

    const float* A;
    const float* Bp;
    const float* biasp;
    float*       Cp;
    int ldb, ldc;

    if (mode == 0) {
        A = Aparam;  // x
        if (n0 < 512) { Bp = Wfx + n0;        biasp = bfx + n0; }
        else          { Bp = Wx  + (n0-512);  biasp = bx  + (n0-512); }
        ldb = 512; ldc = 1024;
        Cp = &g_mid[(size_t)m0 * 1024 + n0];
    } else {
        A = g_w;
        int b = m0 >> 15;   // m0 / 32768
        Bp = &g_P[(size_t)b * INNER_ * C_ + n0];
        biasp = bout + n0;
        ldb = 256; ldc = 256;
        Cp = OutParam + (size_t)m0 * 256 + n0;
    }

    const int tid = threadIdx.x;
    const int tm  = tid >> 4;   // 0..15 -> rows tm*4..+4
    const int tn  = tid & 15;   // 0..15 -> cols tn*8..+8
    const int ar  = tid >> 2;   // 0..63
    const int ac  = tid & 3;    // 0..3

    float acc[4][8];
#pragma unroll
    for (int i = 0; i < 4; i++)
#pragma unroll
        for (int j = 0; j < 8; j++) acc[i][j] = 0.f;

    for (int k0 = 0; k0 < Ktot; k0 += BK) {
        // load A tile (transposed into smem)
        float4 av = *(const float4*)&A[(size_t)(m0 + ar) * lda + k0 + ac * 4];
        As[ac*4+0][ar] = av.x;
        As[ac*4+1][ar] = av.y;
        As[ac*4+2][ar] = av.z;
        As[ac*4+3][ar] = av.w;
        // load B tile
#pragma unroll
        for (int i = tid; i < (BK*BN)/4; i += 256) {
            int r = i >> 5, c = i & 31;
            *(float4*)&Bs[r][c*4] = *(const float4*)&Bp[(size_t)(k0 + r) * ldb + c*4];
        }
        __syncthreads();
#pragma unroll
        for (int kk = 0; kk < BK; kk++) {
            float4 a4  = *(float4*)&As[kk][tm*4];
            float4 b40 = *(float4*)&Bs[kk][tn*8];
            float4 b41 = *(float4*)&Bs[kk][tn*8 + 4];
            float a_[4] = {a4.x, a4.y, a4.z, a4.w};
            float b_[8] = {b40.x, b40.y, b40.z, b40.w, b41.x, b41.y, b41.z, b41.w};
#pragma unroll
            for (int i = 0; i < 4; i++)
#pragma unroll
                for (int j = 0; j < 8; j++) acc[i][j] += a_[i] * b_[j];
        }
        __syncthreads();
    }

    float bias[8];
#pragma unroll
    for (int j = 0; j < 8; j++) bias[j] = biasp[tn*8 + j];
#pragma unroll
    for (int i = 0; i < 4; i++) {
        float4 o0 = {acc[i][0]+bias[0], acc[i][1]+bias[1], acc[i][2]+bias[2], acc[i][3]+bias[3]};
        float4 o1 = {acc[i][4]+bias[4], acc[i][5]+bias[5], acc[i][6]+bias[6], acc[i][7]+bias[7]};
        *(float4*)&Cp[(size_t)(tm*4 + i) * ldc + tn*8]     = o0;
        *(float4*)&Cp[(size_t)(tm*4 + i) * ldc + tn*8 + 4] = o1;
    }
}

// ---------------- K_B: fused logits + softmax + pooling partials ----------------
// grid (H_, N_/256, B_), 256 threads. One head, 256 tokens per CTA.
#define TOK 256
#define SMEM_POOL ((2*TOK*68 + 64*68 + 64) * (int)sizeof(float))

__global__ void __launch_bounds__(256) k_pool(
    const float* __restrict__ Wslice, const float* __restrict__ bslice,
    const float* __restrict__ temperature)
{
    extern __shared__ float sm[];
    float* fxs = sm;                      // [TOK][68]
    float* xws = sm + TOK*68;             // [TOK][68] : xm, reused for w
    float* Ws  = sm + 2*TOK*68;           // [64][68]
    float* bsl = Ws + 64*68;              // [64]

    const int h  = blockIdx.x;
    const int tb = blockIdx.y;
    const int b  = blockIdx.z;
    const int tid = threadIdx.x;
    const int m0  = b * N_ + tb * TOK;

    // stage W_slice (+pad) and b_slice
    for (int i = tid; i < 64*16; i += 256) {
        int r = i >> 4, c = i & 15;
        *(float4*)&Ws[r*68 + c*4] = *(const float4*)&Wslice[r*64 + c*4];
    }
    if (tid < 64) bsl[tid] = bslice[tid];

    // stage fx and xm tiles (coalesced)
    for (int i = tid; i < TOK*16; i += 256) {
        int r = i >> 4, c = i & 15;
        *(float4*)&fxs[r*68 + c*4] = *(const float4*)&g_mid[(size_t)(m0+r)*1024 + h*64 + c*4];
        *(float4*)&xws[r*68 + c*4] = *(const float4*)&g_mid[(size_t)(m0+r)*1024 + 512 + h*64 + c*4];
    }
    __syncthreads();

    // per-token logits + softmax (thread == token)
    float tmp = temperature[h];
    tmp = fminf(fmaxf(tmp, 0.1f), 5.0f);
    const float itemp = 1.0f / tmp;

    float lg[64];
#pragma unroll
    for (int g = 0; g < 64; g++) lg[g] = 0.f;

    const float* xr = &xws[tid * 68];
    for (int k = 0; k < 64; k++) {
        float xv = xr[k];
#pragma unroll
        for (int g4 = 0; g4 < 16; g4++) {
            float4 w4 = *(float4*)&Ws[k*68 + g4*4];
            lg[g4*4+0] += xv * w4.x;
            lg[g4*4+1] += xv * w4.y;
            lg[g4*4+2] += xv * w4.z;
            lg[g4*4+3] += xv * w4.w;
        }
    }
    float mx = -1e30f;
#pragma unroll
    for (int g = 0; g < 64; g++) {
        float l = (lg[g] + bsl[g]) * itemp;
        lg[g] = l;
        mx = fmaxf(mx, l);
    }
    float s = 0.f;
#pragma unroll
    for (int g = 0; g < 64; g++) {
        float e = __expf(lg[g] - mx);
        lg[g] = e;
        s += e;
    }
    const float inv = 1.0f / s;

    float* wr = &xws[tid * 68];                       // reuse xm row (private)
    float* gw = &g_w[(size_t)(m0 + tid) * 512 + h*64];
#pragma unroll
    for (int g4 = 0; g4 < 16; g4++) {
        float4 w4 = {lg[g4*4+0]*inv, lg[g4*4+1]*inv, lg[g4*4+2]*inv, lg[g4*4+3]*inv};
        *(float4*)&wr[g4*4] = w4;
        *(float4*)&gw[g4*4] = w4;
    }
    __syncthreads();

    // pooling: acc[g][d] = sum_t w[t][g] * fx[t][d]   (16 outputs/thread)
    const int g0 = (tid >> 4) * 4;
    const int d0 = (tid & 15) * 4;
    float acc[4][4];
#pragma unroll
    for (int i = 0; i < 4; i++)
#pragma unroll
        for (int j = 0; j < 4; j++) acc[i][j] = 0.f;

    for (int t = 0; t < TOK; t++) {
        float4 wv = *(float4*)&xws[t*68 + g0];
        float4 fv = *(float4*)&fxs[t*68 + d0];
        float w_[4] = {wv.x, wv.y, wv.z, wv.w};
        float f_[4] = {fv.x, fv.y, fv.z, fv.w};
#pragma unroll
        for (int i = 0; i < 4; i++)
#pragma unroll
            for (int j = 0; j < 4; j++) acc[i][j] += w_[i] * f_[j];
    }
    const int base = (b*8 + h) * 64;
#pragma unroll
    for (int i = 0; i < 4; i++)
#pragma unroll
        for (int j = 0; j < 4; j++)
            atomicAdd(&g_st[(base + g0 + i) * 64 + d0 + j], acc[i][j]);

    if (tid < 64) {
        float sn = 0.f;
        for (int t = 0; t < TOK; t++) sn += xws[t*68 + tid];
        atomicAdd(&g_nrm[base + tid], sn);
    }
}

// ---------------- K_C1: tiny attention over slice tokens ----------------
#define SMEM_ATTN ((4*64*65 + 64*64) * (int)sizeof(float))
__global__ void __launch_bounds__(64) k_attn(
    const float* __restrict__ Wq, const float* __restrict__ Wk,
    const float* __restrict__ Wv)
{
    extern __shared__ float sm[];
    float* S  = sm;             // [64][65]
    float* Qs = S  + 64*65;
    float* Ks = Qs + 64*65;
    float* Vs = Ks + 64*65;
    float* Wb = Vs + 64*65;     // [64][64]

    const int h = blockIdx.x, b = blockIdx.y;
    const int g = threadIdx.x;
    const int base = (b*8 + h) * 64;

    const float invn = 1.0f / (g_nrm[base + g] + 1e-5f);
    for (int d = 0; d < 64; d++)
        S[g*65 + d] = g_st[(base + g)*64 + d] * invn;
    __syncthreads();

    const float* Wmats[3] = {Wq, Wk, Wv};
    float* dsts[3] = {Qs, Ks, Vs};
    for (int p = 0; p < 3; p++) {
        for (int d = 0; d < 64; d++) Wb[g*64 + d] = Wmats[p][g*64 + d];
        __syncthreads();
        float a[64];
#pragma unroll
        for (int d = 0; d < 64; d++) a[d] = 0.f;
        for (int k = 0; k < 64; k++) {
            float sv = S[g*65 + k];
#pragma unroll
            for (int d = 0; d < 64; d++) a[d] += sv * Wb[k*64 + d];
        }
#pragma unroll
        for (int d = 0; d < 64; d++) dsts[p][g*65 + d] = a[d];
        __syncthreads();
    }

    float lg[64];
#pragma unroll
    for (int j = 0; j < 64; j++) {
        float dot = 0.f;
#pragma unroll
        for (int d = 0; d < 64; d++) dot += Qs[g*65 + d] * Ks[j*65 + d];
        lg[j] = dot * 0.125f;   // SCALE = 64^-0.5
    }
    float mx = -1e30f;
#pragma unroll
    for (int j = 0; j < 64; j++) mx = fmaxf(mx, lg[j]);
    float s = 0.f;
#pragma unroll
    for (int j = 0; j < 64; j++) { float e = __expf(lg[j] - mx); lg[j] = e; s += e; }
    float inv = 1.0f / s;
#pragma unroll
    for (int j = 0; j < 64; j++) lg[j] *= inv;

    for (int d = 0; d < 64; d++) {
        float o = 0.f;
#pragma unroll
        for (int j = 0; j < 64; j++) o += lg[j] * Vs[j*65 + d];
        g_os[(base + g)*64 + d] = o;
    }
}

// ---------------- K_C2: P[b][h*64+g][c] = os[b,h,g,:] @ W_out rows ----------------
#define SMEM_P ((64*68 + 64*256) * (int)sizeof(float))
__global__ void __launch_bounds__(256) k_P(const float* __restrict__ Wout)
{
    extern __shared__ float sm[];
    float* Os  = sm;            // [64][68]
    float* Wsm = sm + 64*68;    // [64][256]

    const int h = blockIdx.x, b = blockIdx.y;
    const int tid = threadIdx.x;
    const int base = (b*8 + h) * 64;

    for (int i = tid; i < 64*16; i += 256) {
        int r = i >> 4, c = i & 15;
        *(float4*)&Os[r*68 + c*4] = *(const float4*)&g_os[(size_t)(base + r)*64 + c*4];
    }
    for (int i = tid; i < 64*64; i += 256) {
        int r = i >> 6, c = i & 63;
        *(float4*)&Wsm[r*256 + c*4] = *(const float4*)&Wout[(size_t)(h*64 + r)*256 + c*4];
    }
    __syncthreads();

    const int gq = tid >> 3;        // 0..31 -> g = gq*2
    const int cq = tid & 7;         // 0..7  -> c0 = cq*32
    const int g0 = gq * 2;
    const int c0 = cq * 32;

    float acc[2][32];
#pragma unroll
    for (int i = 0; i < 2; i++)
#pragma unroll
        for (int j = 0; j < 32; j++) acc[i][j] = 0.f;

    for (int k = 0; k < 64; k++) {
        float a0 = Os[(g0+0)*68 + k];
        float a1 = Os[(g0+1)*68 + k];
#pragma unroll
        for (int c4 = 0; c4 < 8; c4++) {
            float4 w = *(float4*)&Wsm[k*256 + c0 + c4*4];
            acc[0][c4*4+0] += a0*w.x; acc[0][c4*4+1] += a0*w.y;
            acc[0][c4*4+2] += a0*w.z; acc[0][c4*4+3] += a0*w.w;
            acc[1][c4*4+0] += a1*w.x; acc[1][c4*4+1] += a1*w.y;
            acc[1][c4*4+2] += a1*w.z; acc[1][c4*4+3] += a1*w.w;
        }
    }
    float* Pp = &g_P[(size_t)b * INNER_ * C_];
#pragma unroll
    for (int i = 0; i < 2; i++)
#pragma unroll
        for (int c4 = 0; c4 < 8; c4++) {
            float4 o = {acc[i][c4*4+0], acc[i][c4*4+1], acc[i][c4*4+2], acc[i][c4*4+3]};
            *(float4*)&Pp[(size_t)(h*64 + g0 + i)*256 + c0 + c4*4] = o;
        }
}

// ---------------- launch ----------------
extern "C" void kernel_launch(void* const* d_in, const int* in_sizes, int n_in,
                              void* d_out, int out_size)
{
    const float* x    = (const float*)d_in[0];
    const float* Wfx  = (const float*)d_in[1];
    const float* bfx  = (const float*)d_in[2];
    const float* Wx   = (const float*)d_in[3];
    const float* bx   = (const float*)d_in[4];
    const float* Wsl  = (const float*)d_in[5];
    const float* bsl  = (const float*)d_in[6];
    const float* temp = (const float*)d_in[7];
    const float* Wq   = (const float*)d_in[8];
    const float* Wk   = (const float*)d_in[9];
    const float* Wv   = (const float*)d_in[10];
    const float* Wout = (const float*)d_in[11];
    const float* bout = (const float*)d_in[12];
    float* out = (float*)d_out;

    cudaFuncSetAttribute(k_pool, cudaFuncAttributeMaxDynamicSharedMemorySize, SMEM_POOL);
    cudaFuncSetAttribute(k_attn, cudaFuncAttributeMaxDynamicSharedMemorySize, SMEM_ATTN);
    cudaFuncSetAttribute(k_P,    cudaFuncAttributeMaxDynamicSharedMemorySize, SMEM_P);

    // 0) zero accumulators (inside graph -> re-runs on every replay)
    k_zero<<<(B_*H_*G_*D_ + 255)/256, 256>>>();

    // 1) projections: g_mid = x @ [W_fx | W_x] + bias
    k_gemm<<<dim3(1024/BN, BNTOK/BM), 256>>>(0, x, 256, 256,
                                             Wfx, Wx, bfx, bx, nullptr, nullptr);

    // 2) fused logits/softmax/pooling
    k_pool<<<dim3(H_, N_/TOK, B_), 256, SMEM_POOL>>>(Wsl, bsl, temp);

    // 3) tiny attention over slice tokens
    k_attn<<<dim3(H_, B_), 64, SMEM_ATTN>>>(Wq, Wk, Wv);

    // 4) P precompute
    k_P<<<dim3(H_, B_), 256, SMEM_P>>>(Wout);

    // 5) output: out = g_w @ P[b] + b_out
    k_gemm<<<dim3(256/BN, BNTOK/BM), 256>>>(1, nullptr, 512, 512,
                                            nullptr, nullptr, nullptr, nullptr, bout, out);
}

// round 4
// speedup vs baseline: 1.7746x; 1.7746x over previous
#include <cuda_runtime.h>
#include <cuda_bf16.h>
#include <cstdint>
#include <math.h>

#define B_      4
#define N_      32768
#define C_      256
#define H_      8
#define D_      64
#define G_      64
#define INNER_  512
#define BNTOK   (B_*N_)          // 131072

// single dynamic smem symbol shared by all kernels
extern __shared__ char smem_dyn[];

// ---------------- scratch (device globals; allocation-free) ----------------
__device__ float g_mid[(size_t)BNTOK * 1024];        // [m][0:512]=fx, [512:1024]=xm
__device__ __nv_bfloat16 g_xhi[(size_t)BNTOK * 256]; // x split hi
__device__ __nv_bfloat16 g_xlo[(size_t)BNTOK * 256]; // x split lo
__device__ __nv_bfloat16 g_Whi[1024 * 256];          // [n][k] transposed W_fx|W_x hi
__device__ __nv_bfloat16 g_Wlo[1024 * 256];
__device__ float g_bias0[1024];                      // bfx | bx
__device__ __nv_bfloat16 g_whi[(size_t)BNTOK * 512]; // slice weights hi
__device__ __nv_bfloat16 g_wlo[(size_t)BNTOK * 512];
__device__ __nv_bfloat16 g_Pthi[B_ * C_ * INNER_];   // P_t[b][c][inner] hi
__device__ __nv_bfloat16 g_Ptlo[B_ * C_ * INNER_];
__device__ float g_st [B_*H_*G_*D_];
__device__ float g_nrm[B_*H_*G_];
__device__ float g_os [B_*H_*G_*D_];

// ---------------- helpers ----------------
__device__ __forceinline__ uint32_t smem_to_u32(const void* p) {
    uint32_t a;
    asm("{ .reg .u64 t; cvta.to.shared.u64 t, %1; cvt.u32.u64 %0, t; }" : "=r"(a) : "l"(p));
    return a;
}
__device__ __forceinline__ void ldsm4(uint32_t &r0, uint32_t &r1, uint32_t &r2, uint32_t &r3,
                                      uint32_t addr) {
    asm volatile("ldmatrix.sync.aligned.m8n8.x4.shared.b16 {%0,%1,%2,%3}, [%4];"
        : "=r"(r0), "=r"(r1), "=r"(r2), "=r"(r3) : "r"(addr));
}
__device__ __forceinline__ void mma16816(float* c,
                                         uint32_t a0, uint32_t a1, uint32_t a2, uint32_t a3,
                                         uint32_t b0, uint32_t b1) {
    asm volatile(
        "mma.sync.aligned.m16n8k16.row.col.f32.bf16.bf16.f32 "
        "{%0,%1,%2,%3}, {%4,%5,%6,%7}, {%8,%9}, {%0,%1,%2,%3};"
        : "+f"(c[0]), "+f"(c[1]), "+f"(c[2]), "+f"(c[3])
        : "r"(a0), "r"(a1), "r"(a2), "r"(a3), "r"(b0), "r"(b1));
}
__device__ __forceinline__ void split_one(float a, __nv_bfloat16 &hi, __nv_bfloat16 &lo) {
    hi = __float2bfloat16(a);
    lo = __float2bfloat16(a - __bfloat162float(hi));
}
__device__ __forceinline__ void split_pair(float a, float b, unsigned &hi, unsigned &lo) {
    __nv_bfloat16 ah, al, bh, bl;
    split_one(a, ah, al);
    split_one(b, bh, bl);
    hi = ((unsigned)__bfloat16_as_ushort(bh) << 16) | (unsigned)__bfloat16_as_ushort(ah);
    lo = ((unsigned)__bfloat16_as_ushort(bl) << 16) | (unsigned)__bfloat16_as_ushort(al);
}

// ---------------- K0: zero accumulators ----------------
__global__ void k_zero() {
    int i = blockIdx.x * blockDim.x + threadIdx.x;
    if (i < B_*H_*G_*D_) g_st[i] = 0.f;
    if (i < B_*H_*G_)    g_nrm[i] = 0.f;
}

// ---------------- K_sx: split x into bf16 hi/lo ----------------
__global__ void __launch_bounds__(256) k_split_x(const float* __restrict__ x) {
    size_t i = (size_t)blockIdx.x * 256 + threadIdx.x;   // float4 index
    float4 v = *(const float4*)(x + i * 4);
    unsigned h0, l0, h1, l1;
    split_pair(v.x, v.y, h0, l0);
    split_pair(v.z, v.w, h1, l1);
    *(uint2*)&g_xhi[i * 4] = make_uint2(h0, h1);
    *(uint2*)&g_xlo[i * 4] = make_uint2(l0, l1);
}

// ---------------- K_sw: split + transpose W_fx|W_x, build bias ----------------
__global__ void __launch_bounds__(256) k_split_W(
    const float* __restrict__ Wfx, const float* __restrict__ Wx,
    const float* __restrict__ bfx, const float* __restrict__ bx)
{
    int idx = blockIdx.x * 256 + threadIdx.x;   // 262144 total
    int n = idx & 1023;
    int k = idx >> 10;
    float v = (n < 512) ? Wfx[k * 512 + n] : Wx[k * 512 + (n - 512)];
    __nv_bfloat16 hi, lo;
    split_one(v, hi, lo);
    g_Whi[n * 256 + k] = hi;
    g_Wlo[n * 256 + k] = lo;
    if (blockIdx.x == 0) {
        for (int j = threadIdx.x; j < 1024; j += 256)
            g_bias0[j] = (j < 512) ? bfx[j] : bx[j - 512];
    }
}

// ================= split-bf16 tensor-core GEMM =================
// Out[m][n] = sum_k A[m][k] * B[n][k] + bias[n0+n]
// A: [M][K] bf16 hi/lo, B: [Ntot][K] bf16 hi/lo. 3 passes (hh, hl, lh).
// CTA tile 128x128, K-chunk 64. 8 warps = 2(M) x 4(N); warp tile 64x32.

#define GK_PAD 72                       // halves per smem row (64 + 8 pad)
#define GK_ROWB (GK_PAD * 2)            // 144 bytes
#define GK_ARR (128 * GK_ROWB)          // 18432 bytes per array
#define GK_SMEM (4 * GK_ARR)            // 73728

__global__ void __launch_bounds__(256, 2) k_gemm_ts(
    const __nv_bfloat16* __restrict__ Ahi, const __nv_bfloat16* __restrict__ Alo,
    const __nv_bfloat16* __restrict__ Bhi, const __nv_bfloat16* __restrict__ Blo,
    int K, int b_sel,
    const float* __restrict__ bias,
    float* __restrict__ Out, int ldc)
{
    char* sm = smem_dyn;
    const uint32_t sbase = smem_to_u32(sm);

    const int tid  = threadIdx.x;
    const int wid  = tid >> 5;
    const int lane = tid & 31;
    const int wm   = wid >> 2;          // 0..1
    const int wn   = wid & 3;           // 0..3
    const int m0   = blockIdx.y * 128;
    const int n0   = blockIdx.x * 128;

    const __nv_bfloat16* srcs[4];
    srcs[0] = Ahi + (size_t)m0 * K;
    srcs[1] = Alo + (size_t)m0 * K;
    size_t boff = (size_t)(b_sel ? (m0 >> 15) : 0) * 256 * INNER_ + (size_t)n0 * K;
    srcs[2] = Bhi + boff;
    srcs[3] = Blo + boff;

    float acc[4][4][4];
#pragma unroll
    for (int i = 0; i < 4; i++)
#pragma unroll
        for (int j = 0; j < 4; j++)
#pragma unroll
            for (int e = 0; e < 4; e++) acc[i][j][e] = 0.f;

    // per-lane ldmatrix source coordinates
    const int lrow = lane & 15;
    const int lkq  = (lane >> 4) << 3;  // 0 or 8 (halves)

    const int nch = K >> 6;
    for (int ch = 0; ch < nch; ch++) {
        const int k0 = ch << 6;

        // ---- stage 4 arrays: 128 rows x 64 halves each ----
#pragma unroll
        for (int arr = 0; arr < 4; arr++) {
            const __nv_bfloat16* s = srcs[arr] + k0;
            char* d = sm + arr * GK_ARR;
#pragma unroll
            for (int it = 0; it < 4; it++) {
                int t = tid + it * 256;           // 0..1023
                int row = t >> 3, q = t & 7;
                uint4 v = *(const uint4*)(s + (size_t)row * K + q * 8);
                *(uint4*)(d + row * GK_ROWB + q * 16) = v;
            }
        }
        __syncthreads();

        // ---- 3 passes x 4 k-steps ----
#pragma unroll
        for (int pass = 0; pass < 3; pass++) {
            const uint32_t aoff = sbase + (pass == 2 ? GK_ARR : 0);
            const uint32_t boff2 = sbase + (pass == 1 ? 3 * GK_ARR : 2 * GK_ARR);
#pragma unroll
            for (int ks = 0; ks < 4; ks++) {
                const int kh = ks * 16 + lkq;     // halves
                uint32_t a[4][4];
#pragma unroll
                for (int i = 0; i < 4; i++) {
                    int row = wm * 64 + i * 16 + lrow;
                    ldsm4(a[i][0], a[i][1], a[i][2], a[i][3],
                          aoff + row * GK_ROWB + kh * 2);
                }
                uint32_t b[8];
#pragma unroll
                for (int jp = 0; jp < 2; jp++) {
                    int row = wn * 32 + jp * 16 + lrow;
                    ldsm4(b[jp*4+0], b[jp*4+1], b[jp*4+2], b[jp*4+3],
                          boff2 + row * GK_ROWB + kh * 2);
                }
#pragma unroll
                for (int i = 0; i < 4; i++) {
                    mma16816(acc[i][0], a[i][0], a[i][1], a[i][2], a[i][3], b[0], b[2]);
                    mma16816(acc[i][1], a[i][0], a[i][1], a[i][2], a[i][3], b[1], b[3]);
                    mma16816(acc[i][2], a[i][0], a[i][1], a[i][2], a[i][3], b[4], b[6]);
                    mma16816(acc[i][3], a[i][0], a[i][1], a[i][2], a[i][3], b[5], b[7]);
                }
            }
        }
        __syncthreads();
    }

    // ---- epilogue ----
    const int r0 = lane >> 2;
    const int c0 = (lane & 3) * 2;
#pragma unroll
    for (int j = 0; j < 4; j++) {
        const int col = n0 + wn * 32 + j * 8 + c0;
        const float2 bi = *(const float2*)&bias[col];
#pragma unroll
        for (int i = 0; i < 4; i++) {
            const int row = m0 + wm * 64 + i * 16 + r0;
            float2 o0 = {acc[i][j][0] + bi.x, acc[i][j][1] + bi.y};
            float2 o1 = {acc[i][j][2] + bi.x, acc[i][j][3] + bi.y};
            *(float2*)&Out[(size_t)row * ldc + col] = o0;
            *(float2*)&Out[(size_t)(row + 8) * ldc + col] = o1;
        }
    }
}

// ---------------- K_B: fused logits + softmax + pooling partials ----------------
#define TOK 256
#define SMEM_POOL ((2*TOK*68 + 64*68 + 64) * (int)sizeof(float))

__global__ void __launch_bounds__(256) k_pool(
    const float* __restrict__ Wslice, const float* __restrict__ bslice,
    const float* __restrict__ temperature)
{
    float* sm = (float*)smem_dyn;
    float* fxs = sm;                      // [TOK][68]
    float* xws = sm + TOK*68;             // [TOK][68] : xm, reused for w
    float* Ws  = sm + 2*TOK*68;           // [64][68]
    float* bsl = Ws + 64*68;              // [64]

    const int h  = blockIdx.x;
    const int tb = blockIdx.y;
    const int b  = blockIdx.z;
    const int tid = threadIdx.x;
    const int m0  = b * N_ + tb * TOK;

    for (int i = tid; i < 64*16; i += 256) {
        int r = i >> 4, c = i & 15;
        *(float4*)&Ws[r*68 + c*4] = *(const float4*)&Wslice[r*64 + c*4];
    }
    if (tid < 64) bsl[tid] = bslice[tid];

    for (int i = tid; i < TOK*16; i += 256) {
        int r = i >> 4, c = i & 15;
        *(float4*)&fxs[r*68 + c*4] = *(const float4*)&g_mid[(size_t)(m0+r)*1024 + h*64 + c*4];
        *(float4*)&xws[r*68 + c*4] = *(const float4*)&g_mid[(size_t)(m0+r)*1024 + 512 + h*64 + c*4];
    }
    __syncthreads();

    float tmp = temperature[h];
    tmp = fminf(fmaxf(tmp, 0.1f), 5.0f);
    const float itemp = 1.0f / tmp;

    float lg[64];
#pragma unroll
    for (int g = 0; g < 64; g++) lg[g] = 0.f;

    const float* xr = &xws[tid * 68];
    for (int k = 0; k < 64; k++) {
        float xv = xr[k];
#pragma unroll
        for (int g4 = 0; g4 < 16; g4++) {
            float4 w4 = *(float4*)&Ws[k*68 + g4*4];
            lg[g4*4+0] += xv * w4.x;
            lg[g4*4+1] += xv * w4.y;
            lg[g4*4+2] += xv * w4.z;
            lg[g4*4+3] += xv * w4.w;
        }
    }
    float mx = -1e30f;
#pragma unroll
    for (int g = 0; g < 64; g++) {
        float l = (lg[g] + bsl[g]) * itemp;
        lg[g] = l;
        mx = fmaxf(mx, l);
    }
    float s = 0.f;
#pragma unroll
    for (int g = 0; g < 64; g++) {
        float e = __expf(lg[g] - mx);
        lg[g] = e;
        s += e;
    }
    const float inv = 1.0f / s;

    float* wr = &xws[tid * 68];
    __nv_bfloat16* gwh = &g_whi[(size_t)(m0 + tid) * 512 + h*64];
    __nv_bfloat16* gwl = &g_wlo[(size_t)(m0 + tid) * 512 + h*64];
#pragma unroll
    for (int g4 = 0; g4 < 16; g4++) {
        float4 w4 = {lg[g4*4+0]*inv, lg[g4*4+1]*inv, lg[g4*4+2]*inv, lg[g4*4+3]*inv};
        *(float4*)&wr[g4*4] = w4;
        unsigned h0, l0, h1, l1;
        split_pair(w4.x, w4.y, h0, l0);
        split_pair(w4.z, w4.w, h1, l1);
        *(uint2*)&gwh[g4*4] = make_uint2(h0, h1);
        *(uint2*)&gwl[g4*4] = make_uint2(l0, l1);
    }
    __syncthreads();

    const int g0 = (tid >> 4) * 4;
    const int d0 = (tid & 15) * 4;
    float acc[4][4];
#pragma unroll
    for (int i = 0; i < 4; i++)
#pragma unroll
        for (int j = 0; j < 4; j++) acc[i][j] = 0.f;

    for (int t = 0; t < TOK; t++) {
        float4 wv = *(float4*)&xws[t*68 + g0];
        float4 fv = *(float4*)&fxs[t*68 + d0];
        float w_[4] = {wv.x, wv.y, wv.z, wv.w};
        float f_[4] = {fv.x, fv.y, fv.z, fv.w};
#pragma unroll
        for (int i = 0; i < 4; i++)
#pragma unroll
            for (int j = 0; j < 4; j++) acc[i][j] += w_[i] * f_[j];
    }
    const int base = (b*8 + h) * 64;
#pragma unroll
    for (int i = 0; i < 4; i++)
#pragma unroll
        for (int j = 0; j < 4; j++)
            atomicAdd(&g_st[(base + g0 + i) * 64 + d0 + j], acc[i][j]);

    if (tid < 64) {
        float sn = 0.f;
        for (int t = 0; t < TOK; t++) sn += xws[t*68 + tid];
        atomicAdd(&g_nrm[base + tid], sn);
    }
}

// ---------------- K_C1: tiny attention over slice tokens ----------------
#define SMEM_ATTN ((4*64*65 + 64*64) * (int)sizeof(float))
__global__ void __launch_bounds__(64) k_attn(
    const float* __restrict__ Wq, const float* __restrict__ Wk,
    const float* __restrict__ Wv)
{
    float* sm = (float*)smem_dyn;
    float* S  = sm;
    float* Qs = S  + 64*65;
    float* Ks = Qs + 64*65;
    float* Vs = Ks + 64*65;
    float* Wb = Vs + 64*65;

    const int h = blockIdx.x, b = blockIdx.y;
    const int g = threadIdx.x;
    const int base = (b*8 + h) * 64;

    const float invn = 1.0f / (g_nrm[base + g] + 1e-5f);
    for (int d = 0; d < 64; d++)
        S[g*65 + d] = g_st[(base + g)*64 + d] * invn;
    __syncthreads();

    const float* Wmats[3] = {Wq, Wk, Wv};
    float* dsts[3] = {Qs, Ks, Vs};
    for (int p = 0; p < 3; p++) {
        for (int d = 0; d < 64; d++) Wb[g*64 + d] = Wmats[p][g*64 + d];
        __syncthreads();
        float a[64];
#pragma unroll
        for (int d = 0; d < 64; d++) a[d] = 0.f;
        for (int k = 0; k < 64; k++) {
            float sv = S[g*65 + k];
#pragma unroll
            for (int d = 0; d < 64; d++) a[d] += sv * Wb[k*64 + d];
        }
#pragma unroll
        for (int d = 0; d < 64; d++) dsts[p][g*65 + d] = a[d];
        __syncthreads();
    }

    float lg[64];
#pragma unroll
    for (int j = 0; j < 64; j++) {
        float dot = 0.f;
#pragma unroll
        for (int d = 0; d < 64; d++) dot += Qs[g*65 + d] * Ks[j*65 + d];
        lg[j] = dot * 0.125f;
    }
    float mx = -1e30f;
#pragma unroll
    for (int j = 0; j < 64; j++) mx = fmaxf(mx, lg[j]);
    float s = 0.f;
#pragma unroll
    for (int j = 0; j < 64; j++) { float e = __expf(lg[j] - mx); lg[j] = e; s += e; }
    float inv = 1.0f / s;
#pragma unroll
    for (int j = 0; j < 64; j++) lg[j] *= inv;

    for (int d = 0; d < 64; d++) {
        float o = 0.f;
#pragma unroll
        for (int j = 0; j < 64; j++) o += lg[j] * Vs[j*65 + d];
        g_os[(base + g)*64 + d] = o;
    }
}

// ---------------- K_C2: P_t[b][c][h*64+g] split bf16 ----------------
#define SMEM_P ((64*68 + 64*256) * (int)sizeof(float))
__global__ void __launch_bounds__(256) k_P(const float* __restrict__ Wout)
{
    float* sm = (float*)smem_dyn;
    float* Os  = sm;            // [64][68]
    float* Wsm = sm + 64*68;    // [64][256]

    const int h = blockIdx.x, b = blockIdx.y;
    const int tid = threadIdx.x;
    const int base = (b*8 + h) * 64;

    for (int i = tid; i < 64*16; i += 256) {
        int r = i >> 4, c = i & 15;
        *(float4*)&Os[r*68 + c*4] = *(const float4*)&g_os[(size_t)(base + r)*64 + c*4];
    }
    for (int i = tid; i < 64*64; i += 256) {
        int r = i >> 6, c = i & 63;
        *(float4*)&Wsm[r*256 + c*4] = *(const float4*)&Wout[(size_t)(h*64 + r)*256 + c*4];
    }
    __syncthreads();

    const int gq = tid >> 3;
    const int cq = tid & 7;
    const int g0 = gq * 2;
    const int c0 = cq * 32;

    float acc[2][32];
#pragma unroll
    for (int i = 0; i < 2; i++)
#pragma unroll
        for (int j = 0; j < 32; j++) acc[i][j] = 0.f;

    for (int k = 0; k < 64; k++) {
        float a0 = Os[(g0+0)*68 + k];
        float a1 = Os[(g0+1)*68 + k];
#pragma unroll
        for (int c4 = 0; c4 < 8; c4++) {
            float4 w = *(float4*)&Wsm[k*256 + c0 + c4*4];
            acc[0][c4*4+0] += a0*w.x; acc[0][c4*4+1] += a0*w.y;
            acc[0][c4*4+2] += a0*w.z; acc[0][c4*4+3] += a0*w.w;
            acc[1][c4*4+0] += a1*w.x; acc[1][c4*4+1] += a1*w.y;
            acc[1][c4*4+2] += a1*w.z; acc[1][c4*4+3] += a1*w.w;
        }
    }
    __nv_bfloat16* Ph = &g_Pthi[(size_t)b * C_ * INNER_];
    __nv_bfloat16* Pl = &g_Ptlo[(size_t)b * C_ * INNER_];
#pragma unroll
    for (int i = 0; i < 2; i++)
#pragma unroll
        for (int c4 = 0; c4 < 8; c4++)
#pragma unroll
            for (int e = 0; e < 4; e++) {
                size_t off = (size_t)(c0 + c4*4 + e) * INNER_ + h*64 + g0 + i;
                __nv_bfloat16 hi, lo;
                split_one(acc[i][c4*4+e], hi, lo);
                Ph[off] = hi;
                Pl[off] = lo;
            }
}

// ---------------- launch ----------------
extern "C" void kernel_launch(void* const* d_in, const int* in_sizes, int n_in,
                              void* d_out, int out_size)
{
    const float* x    = (const float*)d_in[0];
    const float* Wfx  = (const float*)d_in[1];
    const float* bfx  = (const float*)d_in[2];
    const float* Wx   = (const float*)d_in[3];
    const float* bx   = (const float*)d_in[4];
    const float* Wsl  = (const float*)d_in[5];
    const float* bsl  = (const float*)d_in[6];
    const float* temp = (const float*)d_in[7];
    const float* Wq   = (const float*)d_in[8];
    const float* Wk   = (const float*)d_in[9];
    const float* Wv   = (const float*)d_in[10];
    const float* Wout = (const float*)d_in[11];
    const float* bout = (const float*)d_in[12];
    float* out = (float*)d_out;

    static bool init = false;
    static float *g_mid_p, *g_bias0_p;
    static __nv_bfloat16 *g_xhi_p, *g_xlo_p, *g_Whi_p, *g_Wlo_p;
    static __nv_bfloat16 *g_whi_p, *g_wlo_p, *g_Pthi_p, *g_Ptlo_p;
    if (!init) {
        cudaGetSymbolAddress((void**)&g_mid_p,   g_mid);
        cudaGetSymbolAddress((void**)&g_bias0_p, g_bias0);
        cudaGetSymbolAddress((void**)&g_xhi_p,   g_xhi);
        cudaGetSymbolAddress((void**)&g_xlo_p,   g_xlo);
        cudaGetSymbolAddress((void**)&g_Whi_p,   g_Whi);
        cudaGetSymbolAddress((void**)&g_Wlo_p,   g_Wlo);
        cudaGetSymbolAddress((void**)&g_whi_p,   g_whi);
        cudaGetSymbolAddress((void**)&g_wlo_p,   g_wlo);
        cudaGetSymbolAddress((void**)&g_Pthi_p,  g_Pthi);
        cudaGetSymbolAddress((void**)&g_Ptlo_p,  g_Ptlo);
        cudaFuncSetAttribute(k_gemm_ts, cudaFuncAttributeMaxDynamicSharedMemorySize, GK_SMEM);
        cudaFuncSetAttribute(k_pool, cudaFuncAttributeMaxDynamicSharedMemorySize, SMEM_POOL);
        cudaFuncSetAttribute(k_attn, cudaFuncAttributeMaxDynamicSharedMemorySize, SMEM_ATTN);
        cudaFuncSetAttribute(k_P,    cudaFuncAttributeMaxDynamicSharedMemorySize, SMEM_P);
        init = true;
    }

    // 0) zero accumulators + operand splitting
    k_zero<<<(B_*H_*G_*D_ + 255)/256, 256>>>();
    k_split_x<<<(BNTOK * 256 / 4) / 256, 256>>>(x);
    k_split_W<<<262144 / 256, 256>>>(Wfx, Wx, bfx, bx);

    // 1) projections: g_mid = x @ [W_fx | W_x] + bias   (tensor cores)
    k_gemm_ts<<<dim3(8, BNTOK/128), 256, GK_SMEM>>>(
        g_xhi_p, g_xlo_p, g_Whi_p, g_Wlo_p, 256, 0, g_bias0_p, g_mid_p, 1024);

    // 2) fused logits/softmax/pooling (+ split weight write)
    k_pool<<<dim3(H_, N_/TOK, B_), 256, SMEM_POOL>>>(Wsl, bsl, temp);

    // 3) tiny attention over slice tokens
    k_attn<<<dim3(H_, B_), 64, SMEM_ATTN>>>(Wq, Wk, Wv);

    // 4) P precompute (transposed + split)
    k_P<<<dim3(H_, B_), 256, SMEM_P>>>(Wout);

    // 5) output: out = w @ P_t^T + b_out   (tensor cores)
    k_gemm_ts<<<dim3(2, BNTOK/128), 256, GK_SMEM>>>(
        g_whi_p, g_wlo_p, g_Pthi_p, g_Ptlo_p, 512, 1, bout, out, 256);
}

// round 5
// speedup vs baseline: 2.8146x; 1.5861x over previous
#include <cuda_runtime.h>
#include <cuda_bf16.h>
#include <cstdint>
#include <math.h>

#define B_      4
#define N_      32768
#define C_      256
#define H_      8
#define D_      64
#define G_      64
#define INNER_  512
#define BNTOK   (B_*N_)          // 131072

// single dynamic smem symbol shared by all kernels
extern __shared__ char smem_dyn[];

// ---------------- scratch (device globals; allocation-free) ----------------
__device__ float g_mid[(size_t)BNTOK * 1024];        // [m][0:512]=fx, [512:1024]=xm
__device__ __nv_bfloat16 g_xhi[(size_t)BNTOK * 256];
__device__ __nv_bfloat16 g_xlo[(size_t)BNTOK * 256];
__device__ __nv_bfloat16 g_Whi[1024 * 256];          // [n][k] transposed W_fx|W_x
__device__ __nv_bfloat16 g_Wlo[1024 * 256];
__device__ float g_bias0[1024];
__device__ __nv_bfloat16 g_whi[(size_t)BNTOK * 512]; // slice weights hi
__device__ __nv_bfloat16 g_wlo[(size_t)BNTOK * 512];
__device__ __nv_bfloat16 g_Pthi[B_ * C_ * INNER_];
__device__ __nv_bfloat16 g_Ptlo[B_ * C_ * INNER_];
__device__ float g_st [B_*H_*G_*D_];
__device__ float g_nrm[B_*H_*G_];
__device__ float g_os [B_*H_*G_*D_];

// ---------------- helpers ----------------
__device__ __forceinline__ uint32_t smem_to_u32(const void* p) {
    uint32_t a;
    asm("{ .reg .u64 t; cvta.to.shared.u64 t, %1; cvt.u32.u64 %0, t; }" : "=r"(a) : "l"(p));
    return a;
}
__device__ __forceinline__ void ldsm4(uint32_t &r0, uint32_t &r1, uint32_t &r2, uint32_t &r3,
                                      uint32_t addr) {
    asm volatile("ldmatrix.sync.aligned.m8n8.x4.shared.b16 {%0,%1,%2,%3}, [%4];"
        : "=r"(r0), "=r"(r1), "=r"(r2), "=r"(r3) : "r"(addr));
}
__device__ __forceinline__ void ldsm4t(uint32_t &r0, uint32_t &r1, uint32_t &r2, uint32_t &r3,
                                       uint32_t addr) {
    asm volatile("ldmatrix.sync.aligned.m8n8.x4.trans.shared.b16 {%0,%1,%2,%3}, [%4];"
        : "=r"(r0), "=r"(r1), "=r"(r2), "=r"(r3) : "r"(addr));
}
__device__ __forceinline__ void mma16816(float* c,
                                         uint32_t a0, uint32_t a1, uint32_t a2, uint32_t a3,
                                         uint32_t b0, uint32_t b1) {
    asm volatile(
        "mma.sync.aligned.m16n8k16.row.col.f32.bf16.bf16.f32 "
        "{%0,%1,%2,%3}, {%4,%5,%6,%7}, {%8,%9}, {%0,%1,%2,%3};"
        : "+f"(c[0]), "+f"(c[1]), "+f"(c[2]), "+f"(c[3])
        : "r"(a0), "r"(a1), "r"(a2), "r"(a3), "r"(b0), "r"(b1));
}
__device__ __forceinline__ void split_one(float a, __nv_bfloat16 &hi, __nv_bfloat16 &lo) {
    hi = __float2bfloat16(a);
    lo = __float2bfloat16(a - __bfloat162float(hi));
}
__device__ __forceinline__ void split_pair(float a, float b, unsigned &hi, unsigned &lo) {
    __nv_bfloat16 ah, al, bh, bl;
    split_one(a, ah, al);
    split_one(b, bh, bl);
    hi = ((unsigned)__bfloat16_as_ushort(bh) << 16) | (unsigned)__bfloat16_as_ushort(ah);
    lo = ((unsigned)__bfloat16_as_ushort(bl) << 16) | (unsigned)__bfloat16_as_ushort(al);
}
#define CP_ASYNC16(dst, src) \
    asm volatile("cp.async.cg.shared.global [%0], [%1], 16;" :: "r"(dst), "l"(src))
#define CP_COMMIT()  asm volatile("cp.async.commit_group;")
#define CP_WAIT1()   asm volatile("cp.async.wait_group 1;")
#define CP_WAIT0()   asm volatile("cp.async.wait_group 0;")

// ---------------- K0: zero accumulators ----------------
__global__ void k_zero() {
    int i = blockIdx.x * blockDim.x + threadIdx.x;
    if (i < B_*H_*G_*D_) g_st[i] = 0.f;
    if (i < B_*H_*G_)    g_nrm[i] = 0.f;
}

// ---------------- K_sx: split x into bf16 hi/lo ----------------
__global__ void __launch_bounds__(256) k_split_x(const float* __restrict__ x) {
    size_t i = (size_t)blockIdx.x * 256 + threadIdx.x;
    float4 v = *(const float4*)(x + i * 4);
    unsigned h0, l0, h1, l1;
    split_pair(v.x, v.y, h0, l0);
    split_pair(v.z, v.w, h1, l1);
    *(uint2*)&g_xhi[i * 4] = make_uint2(h0, h1);
    *(uint2*)&g_xlo[i * 4] = make_uint2(l0, l1);
}

// ---------------- K_sw: split + transpose W_fx|W_x, build bias ----------------
__global__ void __launch_bounds__(256) k_split_W(
    const float* __restrict__ Wfx, const float* __restrict__ Wx,
    const float* __restrict__ bfx, const float* __restrict__ bx)
{
    int idx = blockIdx.x * 256 + threadIdx.x;
    int n = idx & 1023;
    int k = idx >> 10;
    float v = (n < 512) ? Wfx[k * 512 + n] : Wx[k * 512 + (n - 512)];
    __nv_bfloat16 hi, lo;
    split_one(v, hi, lo);
    g_Whi[n * 256 + k] = hi;
    g_Wlo[n * 256 + k] = lo;
    if (blockIdx.x == 0) {
        for (int j = threadIdx.x; j < 1024; j += 256)
            g_bias0[j] = (j < 512) ? bfx[j] : bx[j - 512];
    }
}

// ================= split-bf16 tensor-core GEMM, cp.async pipelined =================
// Out[m][n] = sum_k A[m][k]*B[n][k] + bias[n0+n]; 3 passes fused w/ fragment reuse.
// CTA tile 128x128, K-chunk 32, 2-stage double buffer. 8 warps = 2(M)x4(N), 64x32.

#define GK_ROWB 80                      // 32 halves + 8 pad = 40 halves = 80B
#define GK_ARR  (128 * GK_ROWB)         // 10240
#define GK_STG  (4 * GK_ARR)            // 40960 per stage
#define GK_SMEM (2 * GK_STG)            // 81920

__global__ void __launch_bounds__(256, 2) k_gemm_ts(
    const __nv_bfloat16* __restrict__ Ahi, const __nv_bfloat16* __restrict__ Alo,
    const __nv_bfloat16* __restrict__ Bhi, const __nv_bfloat16* __restrict__ Blo,
    int K, int b_sel,
    const float* __restrict__ bias,
    float* __restrict__ Out, int ldc)
{
    char* sm = smem_dyn;
    const uint32_t sbase = smem_to_u32(sm);

    const int tid  = threadIdx.x;
    const int wid  = tid >> 5;
    const int lane = tid & 31;
    const int wm   = wid >> 2;
    const int wn   = wid & 3;
    const int m0   = blockIdx.y * 128;
    const int n0   = blockIdx.x * 128;

    const __nv_bfloat16* srcs[4];
    srcs[0] = Ahi + (size_t)m0 * K;
    srcs[1] = Alo + (size_t)m0 * K;
    size_t boff = (size_t)(b_sel ? (m0 >> 15) : 0) * 256 * INNER_ + (size_t)n0 * K;
    srcs[2] = Bhi + boff;
    srcs[3] = Blo + boff;

    // staging coords (2 tasks of 16B per array per thread)
    const int srow0 = tid >> 2,        sq0 = tid & 3;
    const int srow1 = (tid + 256) >> 2, sq1 = (tid + 256) & 3;

    float acc[4][4][4];
#pragma unroll
    for (int i = 0; i < 4; i++)
#pragma unroll
        for (int j = 0; j < 4; j++)
#pragma unroll
            for (int e = 0; e < 4; e++) acc[i][j][e] = 0.f;

    const int lrow = lane & 15;
    const int lkq  = (lane >> 4) << 3;
    const int nch  = K >> 5;

    // prologue: stage chunk 0 into stage 0
#pragma unroll
    for (int arr = 0; arr < 4; arr++) {
        const __nv_bfloat16* s = srcs[arr];
        uint32_t d = sbase + arr * GK_ARR;
        CP_ASYNC16(d + srow0 * GK_ROWB + sq0 * 16, s + (size_t)srow0 * K + sq0 * 8);
        CP_ASYNC16(d + srow1 * GK_ROWB + sq1 * 16, s + (size_t)srow1 * K + sq1 * 8);
    }
    CP_COMMIT();

    for (int ch = 0; ch < nch; ch++) {
        if (ch + 1 < nch) {
            const int k1 = (ch + 1) << 5;
            const uint32_t stg = sbase + ((ch + 1) & 1) * GK_STG;
#pragma unroll
            for (int arr = 0; arr < 4; arr++) {
                const __nv_bfloat16* s = srcs[arr] + k1;
                uint32_t d = stg + arr * GK_ARR;
                CP_ASYNC16(d + srow0 * GK_ROWB + sq0 * 16, s + (size_t)srow0 * K + sq0 * 8);
                CP_ASYNC16(d + srow1 * GK_ROWB + sq1 * 16, s + (size_t)srow1 * K + sq1 * 8);
            }
            CP_COMMIT();
            CP_WAIT1();
        } else {
            CP_WAIT0();
        }
        __syncthreads();

        const uint32_t stg  = sbase + (ch & 1) * GK_STG;
        const uint32_t sahi = stg, salo = stg + GK_ARR;
        const uint32_t sbhi = stg + 2 * GK_ARR, sblo = stg + 3 * GK_ARR;

#pragma unroll
        for (int ks = 0; ks < 2; ks++) {
            const int khb = (ks * 16 + lkq) * 2;    // byte offset in row
            uint32_t a[4][4], bh[8], bl[8];
#pragma unroll
            for (int i = 0; i < 4; i++) {
                int row = wm * 64 + i * 16 + lrow;
                ldsm4(a[i][0], a[i][1], a[i][2], a[i][3], sahi + row * GK_ROWB + khb);
            }
#pragma unroll
            for (int jp = 0; jp < 2; jp++) {
                int row = wn * 32 + jp * 16 + lrow;
                ldsm4(bh[jp*4+0], bh[jp*4+1], bh[jp*4+2], bh[jp*4+3],
                      sbhi + row * GK_ROWB + khb);
            }
#pragma unroll
            for (int i = 0; i < 4; i++) {           // hh
                mma16816(acc[i][0], a[i][0], a[i][1], a[i][2], a[i][3], bh[0], bh[2]);
                mma16816(acc[i][1], a[i][0], a[i][1], a[i][2], a[i][3], bh[1], bh[3]);
                mma16816(acc[i][2], a[i][0], a[i][1], a[i][2], a[i][3], bh[4], bh[6]);
                mma16816(acc[i][3], a[i][0], a[i][1], a[i][2], a[i][3], bh[5], bh[7]);
            }
#pragma unroll
            for (int jp = 0; jp < 2; jp++) {
                int row = wn * 32 + jp * 16 + lrow;
                ldsm4(bl[jp*4+0], bl[jp*4+1], bl[jp*4+2], bl[jp*4+3],
                      sblo + row * GK_ROWB + khb);
            }
#pragma unroll
            for (int i = 0; i < 4; i++) {           // hl
                mma16816(acc[i][0], a[i][0], a[i][1], a[i][2], a[i][3], bl[0], bl[2]);
                mma16816(acc[i][1], a[i][0], a[i][1], a[i][2], a[i][3], bl[1], bl[3]);
                mma16816(acc[i][2], a[i][0], a[i][1], a[i][2], a[i][3], bl[4], bl[6]);
                mma16816(acc[i][3], a[i][0], a[i][1], a[i][2], a[i][3], bl[5], bl[7]);
            }
#pragma unroll
            for (int i = 0; i < 4; i++) {
                int row = wm * 64 + i * 16 + lrow;
                ldsm4(a[i][0], a[i][1], a[i][2], a[i][3], salo + row * GK_ROWB + khb);
            }
#pragma unroll
            for (int i = 0; i < 4; i++) {           // lh
                mma16816(acc[i][0], a[i][0], a[i][1], a[i][2], a[i][3], bh[0], bh[2]);
                mma16816(acc[i][1], a[i][0], a[i][1], a[i][2], a[i][3], bh[1], bh[3]);
                mma16816(acc[i][2], a[i][0], a[i][1], a[i][2], a[i][3], bh[4], bh[6]);
                mma16816(acc[i][3], a[i][0], a[i][1], a[i][2], a[i][3], bh[5], bh[7]);
            }
        }
        __syncthreads();
    }

    // ---- epilogue ----
    const int r0 = lane >> 2;
    const int c0 = (lane & 3) * 2;
#pragma unroll
    for (int j = 0; j < 4; j++) {
        const int col = n0 + wn * 32 + j * 8 + c0;
        const float2 bi = *(const float2*)&bias[col];
#pragma unroll
        for (int i = 0; i < 4; i++) {
            const int row = m0 + wm * 64 + i * 16 + r0;
            float2 o0 = {acc[i][j][0] + bi.x, acc[i][j][1] + bi.y};
            float2 o1 = {acc[i][j][2] + bi.x, acc[i][j][3] + bi.y};
            *(float2*)&Out[(size_t)row * ldc + col] = o0;
            *(float2*)&Out[(size_t)(row + 8) * ldc + col] = o1;
        }
    }
}

// ================= K_B: tensorized fused logits+softmax+pooling =================
// One CTA = one (b, h) x 256 tokens. 256 threads (8 warps).
// Phase 1: L[256x64] = xm @ Ws^T  (split-bf16, 3 pass) -> softmax in regs -> w
// Phase 2: st[64x64] = w^T @ fx   (split-bf16, 3 pass) -> atomicAdd partials

#define TOK 256
#define PXM_HI 0                         // [256][72] bf16 (xm, then fx)
#define PXM_LO (PXM_HI + 256*144)
#define PWS_HI (PXM_LO + 256*144)        // [64][72] bf16 (Wslice^T)
#define PWS_LO (PWS_HI + 64*144)
#define PWT_HI (PWS_LO + 64*144)         // [64][264] bf16 (w^T)
#define PWT_LO (PWT_HI + 64*528)
#define PBSL   (PWT_LO + 64*528)         // 64 fp32
#define PNRM   (PBSL + 256)              // 64*4 fp32
#define SMEM_POOL (PNRM + 1024)

__global__ void __launch_bounds__(256) k_pool(
    const float* __restrict__ Wslice, const float* __restrict__ bslice,
    const float* __restrict__ temperature)
{
    char* sm = smem_dyn;
    const uint32_t sbase = smem_to_u32(sm);
    float* bslf = (float*)(sm + PBSL);
    float* nrmp = (float*)(sm + PNRM);

    const int h  = blockIdx.x;
    const int tb = blockIdx.y;
    const int b  = blockIdx.z;
    const int tid = threadIdx.x;
    const int wid = tid >> 5;
    const int lane = tid & 31;
    const int m0  = b * N_ + tb * TOK;
    const int lrow = lane & 15;
    const int lkq  = (lane >> 4) << 3;

    // ---- stage xm (split) ----
#pragma unroll
    for (int it = 0; it < 16; it++) {
        int i = tid + it * 256;          // 4096 float4 tasks
        int r = i >> 4, c = i & 15;
        float4 v = *(const float4*)&g_mid[(size_t)(m0+r)*1024 + 512 + h*64 + c*4];
        unsigned h0, l0, h1, l1;
        split_pair(v.x, v.y, h0, l0);
        split_pair(v.z, v.w, h1, l1);
        *(uint2*)(sm + PXM_HI + r*144 + c*8) = make_uint2(h0, h1);
        *(uint2*)(sm + PXM_LO + r*144 + c*8) = make_uint2(l0, l1);
    }
    // ---- stage Ws^T (split, transposed) ----
#pragma unroll
    for (int it = 0; it < 16; it++) {
        int i = tid + it * 256;          // 4096 scalars
        int d = i >> 6, g = i & 63;
        float v = Wslice[d*64 + g];
        __nv_bfloat16 hi, lo;
        split_one(v, hi, lo);
        *(__nv_bfloat16*)(sm + PWS_HI + g*144 + d*2) = hi;
        *(__nv_bfloat16*)(sm + PWS_LO + g*144 + d*2) = lo;
    }
    if (tid < 64) bslf[tid] = bslice[tid];
    __syncthreads();

    // ---- phase 1 MMA: 256x64x64, warp tile 32x64 ----
    float acc[2][8][4];
#pragma unroll
    for (int i = 0; i < 2; i++)
#pragma unroll
        for (int j = 0; j < 8; j++)
#pragma unroll
            for (int e = 0; e < 4; e++) acc[i][j][e] = 0.f;

#pragma unroll
    for (int ks = 0; ks < 4; ks++) {
        const int khb = (ks * 16 + lkq) * 2;
        uint32_t a[2][4], bh[16], bl[16];
#pragma unroll
        for (int i = 0; i < 2; i++) {
            int row = wid * 32 + i * 16 + lrow;
            ldsm4(a[i][0], a[i][1], a[i][2], a[i][3], sbase + PXM_HI + row*144 + khb);
        }
#pragma unroll
        for (int jp = 0; jp < 4; jp++) {
            int row = jp * 16 + lrow;
            ldsm4(bh[jp*4+0], bh[jp*4+1], bh[jp*4+2], bh[jp*4+3],
                  sbase + PWS_HI + row*144 + khb);
        }
#pragma unroll
        for (int i = 0; i < 2; i++)
#pragma unroll
            for (int jj = 0; jj < 8; jj++) {
                int jp = jj >> 1, o = jj & 1;
                mma16816(acc[i][jj], a[i][0], a[i][1], a[i][2], a[i][3],
                         bh[jp*4+o], bh[jp*4+o+2]);
            }
#pragma unroll
        for (int jp = 0; jp < 4; jp++) {
            int row = jp * 16 + lrow;
            ldsm4(bl[jp*4+0], bl[jp*4+1], bl[jp*4+2], bl[jp*4+3],
                  sbase + PWS_LO + row*144 + khb);
        }
#pragma unroll
        for (int i = 0; i < 2; i++)
#pragma unroll
            for (int jj = 0; jj < 8; jj++) {
                int jp = jj >> 1, o = jj & 1;
                mma16816(acc[i][jj], a[i][0], a[i][1], a[i][2], a[i][3],
                         bl[jp*4+o], bl[jp*4+o+2]);
            }
#pragma unroll
        for (int i = 0; i < 2; i++) {
            int row = wid * 32 + i * 16 + lrow;
            ldsm4(a[i][0], a[i][1], a[i][2], a[i][3], sbase + PXM_LO + row*144 + khb);
        }
#pragma unroll
        for (int i = 0; i < 2; i++)
#pragma unroll
            for (int jj = 0; jj < 8; jj++) {
                int jp = jj >> 1, o = jj & 1;
                mma16816(acc[i][jj], a[i][0], a[i][1], a[i][2], a[i][3],
                         bh[jp*4+o], bh[jp*4+o+2]);
            }
    }
    __syncthreads();   // done reading XM; will be overwritten by fx below

    // ---- softmax over g (in registers, quad shuffles) ----
    float tmp = temperature[h];
    tmp = fminf(fmaxf(tmp, 0.1f), 5.0f);
    const float itemp = 1.0f / tmp;

#pragma unroll
    for (int i = 0; i < 2; i++)
#pragma unroll
        for (int j = 0; j < 8; j++) {
            float2 bi = *(float2*)&bslf[j*8 + (lane & 3)*2];
            acc[i][j][0] = (acc[i][j][0] + bi.x) * itemp;
            acc[i][j][1] = (acc[i][j][1] + bi.y) * itemp;
            acc[i][j][2] = (acc[i][j][2] + bi.x) * itemp;
            acc[i][j][3] = (acc[i][j][3] + bi.y) * itemp;
        }
    float inv0[2], inv1[2];
#pragma unroll
    for (int i = 0; i < 2; i++) {
        float m0v = -1e30f, m1v = -1e30f;
#pragma unroll
        for (int j = 0; j < 8; j++) {
            m0v = fmaxf(m0v, fmaxf(acc[i][j][0], acc[i][j][1]));
            m1v = fmaxf(m1v, fmaxf(acc[i][j][2], acc[i][j][3]));
        }
        m0v = fmaxf(m0v, __shfl_xor_sync(0xffffffff, m0v, 1));
        m0v = fmaxf(m0v, __shfl_xor_sync(0xffffffff, m0v, 2));
        m1v = fmaxf(m1v, __shfl_xor_sync(0xffffffff, m1v, 1));
        m1v = fmaxf(m1v, __shfl_xor_sync(0xffffffff, m1v, 2));
        float s0 = 0.f, s1 = 0.f;
#pragma unroll
        for (int j = 0; j < 8; j++) {
            acc[i][j][0] = __expf(acc[i][j][0] - m0v);
            acc[i][j][1] = __expf(acc[i][j][1] - m0v);
            acc[i][j][2] = __expf(acc[i][j][2] - m1v);
            acc[i][j][3] = __expf(acc[i][j][3] - m1v);
            s0 += acc[i][j][0] + acc[i][j][1];
            s1 += acc[i][j][2] + acc[i][j][3];
        }
        s0 += __shfl_xor_sync(0xffffffff, s0, 1);
        s0 += __shfl_xor_sync(0xffffffff, s0, 2);
        s1 += __shfl_xor_sync(0xffffffff, s1, 1);
        s1 += __shfl_xor_sync(0xffffffff, s1, 2);
        inv0[i] = 1.0f / s0;
        inv1[i] = 1.0f / s1;
    }

    // ---- write w: to WT smem (split, [g][t]) and to g_w gmem (split) ----
    {
        const int r = lane >> 2;
#pragma unroll
        for (int i = 0; i < 2; i++) {
            int t0 = wid * 32 + i * 16 + r;
            int t1 = t0 + 8;
#pragma unroll
            for (int j = 0; j < 8; j++) {
                int c = j * 8 + (lane & 3) * 2;
                float w00 = acc[i][j][0] * inv0[i], w01 = acc[i][j][1] * inv0[i];
                float w10 = acc[i][j][2] * inv1[i], w11 = acc[i][j][3] * inv1[i];
                unsigned h0, l0, h1, l1;
                split_pair(w00, w01, h0, l0);
                split_pair(w10, w11, h1, l1);
                // gmem (coalesced-ish 4B stores)
                *(unsigned*)&g_whi[(size_t)(m0 + t0)*512 + h*64 + c] = h0;
                *(unsigned*)&g_wlo[(size_t)(m0 + t0)*512 + h*64 + c] = l0;
                *(unsigned*)&g_whi[(size_t)(m0 + t1)*512 + h*64 + c] = h1;
                *(unsigned*)&g_wlo[(size_t)(m0 + t1)*512 + h*64 + c] = l1;
                // WT smem [g][t] scalar stores
                *(__nv_bfloat16*)(sm + PWT_HI + c*528 + t0*2)     = __ushort_as_bfloat16((unsigned short)(h0 & 0xffff));
                *(__nv_bfloat16*)(sm + PWT_HI + (c+1)*528 + t0*2) = __ushort_as_bfloat16((unsigned short)(h0 >> 16));
                *(__nv_bfloat16*)(sm + PWT_LO + c*528 + t0*2)     = __ushort_as_bfloat16((unsigned short)(l0 & 0xffff));
                *(__nv_bfloat16*)(sm + PWT_LO + (c+1)*528 + t0*2) = __ushort_as_bfloat16((unsigned short)(l0 >> 16));
                *(__nv_bfloat16*)(sm + PWT_HI + c*528 + t1*2)     = __ushort_as_bfloat16((unsigned short)(h1 & 0xffff));
                *(__nv_bfloat16*)(sm + PWT_HI + (c+1)*528 + t1*2) = __ushort_as_bfloat16((unsigned short)(h1 >> 16));
                *(__nv_bfloat16*)(sm + PWT_LO + c*528 + t1*2)     = __ushort_as_bfloat16((unsigned short)(l1 & 0xffff));
                *(__nv_bfloat16*)(sm + PWT_LO + (c+1)*528 + t1*2) = __ushort_as_bfloat16((unsigned short)(l1 >> 16));
            }
        }
    }

    // ---- stage fx into XM buffer (overwrite) ----
    __syncthreads();
#pragma unroll
    for (int it = 0; it < 16; it++) {
        int i = tid + it * 256;
        int r = i >> 4, c = i & 15;
        float4 v = *(const float4*)&g_mid[(size_t)(m0+r)*1024 + h*64 + c*4];
        unsigned h0, l0, h1, l1;
        split_pair(v.x, v.y, h0, l0);
        split_pair(v.z, v.w, h1, l1);
        *(uint2*)(sm + PXM_HI + r*144 + c*8) = make_uint2(h0, h1);
        *(uint2*)(sm + PXM_LO + r*144 + c*8) = make_uint2(l0, l1);
    }
    // ---- norm partial sums (w^T row sums) ----
    {
        int g = tid & 63, q = tid >> 6;
        float s = 0.f;
        const __nv_bfloat16* ph = (const __nv_bfloat16*)(sm + PWT_HI + g*528);
        const __nv_bfloat16* pl = (const __nv_bfloat16*)(sm + PWT_LO + g*528);
#pragma unroll 8
        for (int t = q*64; t < q*64 + 64; t++)
            s += __bfloat162float(ph[t]) + __bfloat162float(pl[t]);
        nrmp[q*64 + g] = s;
    }
    __syncthreads();
    if (tid < 64) {
        float s = nrmp[tid] + nrmp[64+tid] + nrmp[128+tid] + nrmp[192+tid];
        atomicAdd(&g_nrm[(b*8 + h)*64 + tid], s);
    }

    // ---- phase 2 MMA: st[64x64] = w^T @ fx, K=256; warp tile 32x16 ----
    const int wm2 = wid >> 2;            // 0..1 (g)
    const int wn2 = wid & 3;             // 0..3 (d)
    float ac2[2][2][4];
#pragma unroll
    for (int i = 0; i < 2; i++)
#pragma unroll
        for (int j = 0; j < 2; j++)
#pragma unroll
            for (int e = 0; e < 4; e++) ac2[i][j][e] = 0.f;

#pragma unroll
    for (int ks = 0; ks < 16; ks++) {
        const int khb = (ks * 16 + lkq) * 2;     // t halves -> bytes (WT row)
        uint32_t a[2][4], bhv[4], blv[4];
#pragma unroll
        for (int i = 0; i < 2; i++) {
            int row = wm2 * 32 + i * 16 + lrow;
            ldsm4(a[i][0], a[i][1], a[i][2], a[i][3], sbase + PWT_HI + row*528 + khb);
        }
        // B from fx [t][d] via ldsm.trans: lanes cover 16 t-rows x 2 d-halves
        {
            int trow = ks * 16 + lrow;
            uint32_t addr = sbase + PXM_HI + trow*144 + (wn2*16 + lkq)*2;
            ldsm4t(bhv[0], bhv[1], bhv[2], bhv[3], addr);
        }
#pragma unroll
        for (int i = 0; i < 2; i++) {
            mma16816(ac2[i][0], a[i][0], a[i][1], a[i][2], a[i][3], bhv[0], bhv[1]);
            mma16816(ac2[i][1], a[i][0], a[i][1], a[i][2], a[i][3], bhv[2], bhv[3]);
        }
        {
            int trow = ks * 16 + lrow;
            uint32_t addr = sbase + PXM_LO + trow*144 + (wn2*16 + lkq)*2;
            ldsm4t(blv[0], blv[1], blv[2], blv[3], addr);
        }
#pragma unroll
        for (int i = 0; i < 2; i++) {
            mma16816(ac2[i][0], a[i][0], a[i][1], a[i][2], a[i][3], blv[0], blv[1]);
            mma16816(ac2[i][1], a[i][0], a[i][1], a[i][2], a[i][3], blv[2], blv[3]);
        }
#pragma unroll
        for (int i = 0; i < 2; i++) {
            int row = wm2 * 32 + i * 16 + lrow;
            ldsm4(a[i][0], a[i][1], a[i][2], a[i][3], sbase + PWT_LO + row*528 + khb);
        }
#pragma unroll
        for (int i = 0; i < 2; i++) {
            mma16816(ac2[i][0], a[i][0], a[i][1], a[i][2], a[i][3], bhv[0], bhv[1]);
            mma16816(ac2[i][1], a[i][0], a[i][1], a[i][2], a[i][3], bhv[2], bhv[3]);
        }
    }

    // ---- atomic partial reduction into g_st ----
    {
        const int base = (b*8 + h) * 64;
        const int r = lane >> 2;
        const int cq = (lane & 3) * 2;
#pragma unroll
        for (int i = 0; i < 2; i++) {
            int g0r = wm2 * 32 + i * 16 + r;
#pragma unroll
            for (int jj = 0; jj < 2; jj++) {
                int d = wn2 * 16 + jj * 8 + cq;
                atomicAdd(&g_st[(base + g0r)*64 + d],     ac2[i][jj][0]);
                atomicAdd(&g_st[(base + g0r)*64 + d + 1], ac2[i][jj][1]);
                atomicAdd(&g_st[(base + g0r + 8)*64 + d],     ac2[i][jj][2]);
                atomicAdd(&g_st[(base + g0r + 8)*64 + d + 1], ac2[i][jj][3]);
            }
        }
    }
}

// ---------------- K_C1: tiny attention over slice tokens ----------------
#define SMEM_ATTN ((4*64*65 + 64*64) * (int)sizeof(float))
__global__ void __launch_bounds__(64) k_attn(
    const float* __restrict__ Wq, const float* __restrict__ Wk,
    const float* __restrict__ Wv)
{
    float* sm = (float*)smem_dyn;
    float* S  = sm;
    float* Qs = S  + 64*65;
    float* Ks = Qs + 64*65;
    float* Vs = Ks + 64*65;
    float* Wb = Vs + 64*65;

    const int h = blockIdx.x, b = blockIdx.y;
    const int g = threadIdx.x;
    const int base = (b*8 + h) * 64;

    const float invn = 1.0f / (g_nrm[base + g] + 1e-5f);
    for (int d = 0; d < 64; d++)
        S[g*65 + d] = g_st[(base + g)*64 + d] * invn;
    __syncthreads();

    const float* Wmats[3] = {Wq, Wk, Wv};
    float* dsts[3] = {Qs, Ks, Vs};
    for (int p = 0; p < 3; p++) {
        for (int d = 0; d < 64; d++) Wb[g*64 + d] = Wmats[p][g*64 + d];
        __syncthreads();
        float a[64];
#pragma unroll
        for (int d = 0; d < 64; d++) a[d] = 0.f;
        for (int k = 0; k < 64; k++) {
            float sv = S[g*65 + k];
#pragma unroll
            for (int d = 0; d < 64; d++) a[d] += sv * Wb[k*64 + d];
        }
#pragma unroll
        for (int d = 0; d < 64; d++) dsts[p][g*65 + d] = a[d];
        __syncthreads();
    }

    float lg[64];
#pragma unroll
    for (int j = 0; j < 64; j++) {
        float dot = 0.f;
#pragma unroll
        for (int d = 0; d < 64; d++) dot += Qs[g*65 + d] * Ks[j*65 + d];
        lg[j] = dot * 0.125f;
    }
    float mx = -1e30f;
#pragma unroll
    for (int j = 0; j < 64; j++) mx = fmaxf(mx, lg[j]);
    float s = 0.f;
#pragma unroll
    for (int j = 0; j < 64; j++) { float e = __expf(lg[j] - mx); lg[j] = e; s += e; }
    float inv = 1.0f / s;
#pragma unroll
    for (int j = 0; j < 64; j++) lg[j] *= inv;

    for (int d = 0; d < 64; d++) {
        float o = 0.f;
#pragma unroll
        for (int j = 0; j < 64; j++) o += lg[j] * Vs[j*65 + d];
        g_os[(base + g)*64 + d] = o;
    }
}

// ---------------- K_C2: P_t[b][c][h*64+g] split bf16 ----------------
#define SMEM_P ((64*68 + 64*256) * (int)sizeof(float))
__global__ void __launch_bounds__(256) k_P(const float* __restrict__ Wout)
{
    float* sm = (float*)smem_dyn;
    float* Os  = sm;
    float* Wsm = sm + 64*68;

    const int h = blockIdx.x, b = blockIdx.y;
    const int tid = threadIdx.x;
    const int base = (b*8 + h) * 64;

    for (int i = tid; i < 64*16; i += 256) {
        int r = i >> 4, c = i & 15;
        *(float4*)&Os[r*68 + c*4] = *(const float4*)&g_os[(size_t)(base + r)*64 + c*4];
    }
    for (int i = tid; i < 64*64; i += 256) {
        int r = i >> 6, c = i & 63;
        *(float4*)&Wsm[r*256 + c*4] = *(const float4*)&Wout[(size_t)(h*64 + r)*256 + c*4];
    }
    __syncthreads();

    const int gq = tid >> 3;
    const int cq = tid & 7;
    const int g0 = gq * 2;
    const int c0 = cq * 32;

    float acc[2][32];
#pragma unroll
    for (int i = 0; i < 2; i++)
#pragma unroll
        for (int j = 0; j < 32; j++) acc[i][j] = 0.f;

    for (int k = 0; k < 64; k++) {
        float a0 = Os[(g0+0)*68 + k];
        float a1 = Os[(g0+1)*68 + k];
#pragma unroll
        for (int c4 = 0; c4 < 8; c4++) {
            float4 w = *(float4*)&Wsm[k*256 + c0 + c4*4];
            acc[0][c4*4+0] += a0*w.x; acc[0][c4*4+1] += a0*w.y;
            acc[0][c4*4+2] += a0*w.z; acc[0][c4*4+3] += a0*w.w;
            acc[1][c4*4+0] += a1*w.x; acc[1][c4*4+1] += a1*w.y;
            acc[1][c4*4+2] += a1*w.z; acc[1][c4*4+3] += a1*w.w;
        }
    }
    __nv_bfloat16* Ph = &g_Pthi[(size_t)b * C_ * INNER_];
    __nv_bfloat16* Pl = &g_Ptlo[(size_t)b * C_ * INNER_];
#pragma unroll
    for (int i = 0; i < 2; i++)
#pragma unroll
        for (int c4 = 0; c4 < 8; c4++)
#pragma unroll
            for (int e = 0; e < 4; e++) {
                size_t off = (size_t)(c0 + c4*4 + e) * INNER_ + h*64 + g0 + i;
                __nv_bfloat16 hi, lo;
                split_one(acc[i][c4*4+e], hi, lo);
                Ph[off] = hi;
                Pl[off] = lo;
            }
}

// ---------------- launch ----------------
extern "C" void kernel_launch(void* const* d_in, const int* in_sizes, int n_in,
                              void* d_out, int out_size)
{
    const float* x    = (const float*)d_in[0];
    const float* Wfx  = (const float*)d_in[1];
    const float* bfx  = (const float*)d_in[2];
    const float* Wx   = (const float*)d_in[3];
    const float* bx   = (const float*)d_in[4];
    const float* Wsl  = (const float*)d_in[5];
    const float* bsl  = (const float*)d_in[6];
    const float* temp = (const float*)d_in[7];
    const float* Wq   = (const float*)d_in[8];
    const float* Wk   = (const float*)d_in[9];
    const float* Wv   = (const float*)d_in[10];
    const float* Wout = (const float*)d_in[11];
    const float* bout = (const float*)d_in[12];
    float* out = (float*)d_out;

    static bool init = false;
    static float *g_mid_p, *g_bias0_p;
    static __nv_bfloat16 *g_xhi_p, *g_xlo_p, *g_Whi_p, *g_Wlo_p;
    static __nv_bfloat16 *g_whi_p, *g_wlo_p, *g_Pthi_p, *g_Ptlo_p;
    if (!init) {
        cudaGetSymbolAddress((void**)&g_mid_p,   g_mid);
        cudaGetSymbolAddress((void**)&g_bias0_p, g_bias0);
        cudaGetSymbolAddress((void**)&g_xhi_p,   g_xhi);
        cudaGetSymbolAddress((void**)&g_xlo_p,   g_xlo);
        cudaGetSymbolAddress((void**)&g_Whi_p,   g_Whi);
        cudaGetSymbolAddress((void**)&g_Wlo_p,   g_Wlo);
        cudaGetSymbolAddress((void**)&g_whi_p,   g_whi);
        cudaGetSymbolAddress((void**)&g_wlo_p,   g_wlo);
        cudaGetSymbolAddress((void**)&g_Pthi_p,  g_Pthi);
        cudaGetSymbolAddress((void**)&g_Ptlo_p,  g_Ptlo);
        cudaFuncSetAttribute(k_gemm_ts, cudaFuncAttributeMaxDynamicSharedMemorySize, GK_SMEM);
        cudaFuncSetAttribute(k_pool, cudaFuncAttributeMaxDynamicSharedMemorySize, SMEM_POOL);
        cudaFuncSetAttribute(k_attn, cudaFuncAttributeMaxDynamicSharedMemorySize, SMEM_ATTN);
        cudaFuncSetAttribute(k_P,    cudaFuncAttributeMaxDynamicSharedMemorySize, SMEM_P);
        init = true;
    }

    // 0) zero accumulators + operand splitting
    k_zero<<<(B_*H_*G_*D_ + 255)/256, 256>>>();
    k_split_x<<<(BNTOK * 256 / 4) / 256, 256>>>(x);
    k_split_W<<<262144 / 256, 256>>>(Wfx, Wx, bfx, bx);

    // 1) projections (tensor cores, pipelined)
    k_gemm_ts<<<dim3(8, BNTOK/128), 256, GK_SMEM>>>(
        g_xhi_p, g_xlo_p, g_Whi_p, g_Wlo_p, 256, 0, g_bias0_p, g_mid_p, 1024);

    // 2) fused logits/softmax/pooling (tensor cores)
    k_pool<<<dim3(H_, N_/TOK, B_), 256, SMEM_POOL>>>(Wsl, bsl, temp);

    // 3) tiny attention over slice tokens
    k_attn<<<dim3(H_, B_), 64, SMEM_ATTN>>>(Wq, Wk, Wv);

    // 4) P precompute (transposed + split)
    k_P<<<dim3(H_, B_), 256, SMEM_P>>>(Wout);

    // 5) output GEMM (tensor cores, pipelined)
    k_gemm_ts<<<dim3(2, BNTOK/128), 256, GK_SMEM>>>(
        g_whi_p, g_wlo_p, g_Pthi_p, g_Ptlo_p, 512, 1, bout, out, 256);
}

// round 7
// speedup vs baseline: 3.4252x; 1.2169x over previous
#include <cuda_runtime.h>
#include <cuda_bf16.h>
#include <cstdint>
#include <math.h>

#define B_      4
#define N_      32768
#define C_      256
#define H_      8
#define D_      64
#define G_      64
#define INNER_  512
#define BNTOK   (B_*N_)          // 131072

// single dynamic smem symbol shared by all kernels
extern __shared__ char smem_dyn[];

// ---------------- scratch (device globals; allocation-free) ----------------
__device__ __nv_bfloat16 g_fxhi[(size_t)BNTOK * 512]; // fx split hi  [m][512]
__device__ __nv_bfloat16 g_fxlo[(size_t)BNTOK * 512]; // fx split lo
__device__ __nv_bfloat16 g_xmhi[(size_t)BNTOK * 512]; // xm hi only
__device__ __nv_bfloat16 g_xhi[(size_t)BNTOK * 256];
__device__ __nv_bfloat16 g_xlo[(size_t)BNTOK * 256];
__device__ __nv_bfloat16 g_Whi[1024 * 256];          // [n][k] transposed W_fx|W_x
__device__ __nv_bfloat16 g_Wlo[1024 * 256];
__device__ float g_bias0[1024];
__device__ __nv_bfloat16 g_whi[(size_t)BNTOK * 512]; // slice weights hi
__device__ __nv_bfloat16 g_wlo[(size_t)BNTOK * 512];
__device__ __nv_bfloat16 g_Pthi[B_ * C_ * INNER_];
__device__ __nv_bfloat16 g_Ptlo[B_ * C_ * INNER_];
__device__ float g_st [B_*H_*G_*D_];
__device__ float g_nrm[B_*H_*G_];
__device__ float g_os [B_*H_*G_*D_];

// ---------------- helpers ----------------
__device__ __forceinline__ uint32_t smem_to_u32(const void* p) {
    uint32_t a;
    asm("{ .reg .u64 t; cvta.to.shared.u64 t, %1; cvt.u32.u64 %0, t; }" : "=r"(a) : "l"(p));
    return a;
}
__device__ __forceinline__ void ldsm4(uint32_t &r0, uint32_t &r1, uint32_t &r2, uint32_t &r3,
                                      uint32_t addr) {
    asm volatile("ldmatrix.sync.aligned.m8n8.x4.shared.b16 {%0,%1,%2,%3}, [%4];"
        : "=r"(r0), "=r"(r1), "=r"(r2), "=r"(r3) : "r"(addr));
}
__device__ __forceinline__ void ldsm4t(uint32_t &r0, uint32_t &r1, uint32_t &r2, uint32_t &r3,
                                       uint32_t addr) {
    asm volatile("ldmatrix.sync.aligned.m8n8.x4.trans.shared.b16 {%0,%1,%2,%3}, [%4];"
        : "=r"(r0), "=r"(r1), "=r"(r2), "=r"(r3) : "r"(addr));
}
__device__ __forceinline__ void mma16816(float* c,
                                         uint32_t a0, uint32_t a1, uint32_t a2, uint32_t a3,
                                         uint32_t b0, uint32_t b1) {
    asm volatile(
        "mma.sync.aligned.m16n8k16.row.col.f32.bf16.bf16.f32 "
        "{%0,%1,%2,%3}, {%4,%5,%6,%7}, {%8,%9}, {%0,%1,%2,%3};"
        : "+f"(c[0]), "+f"(c[1]), "+f"(c[2]), "+f"(c[3])
        : "r"(a0), "r"(a1), "r"(a2), "r"(a3), "r"(b0), "r"(b1));
}
__device__ __forceinline__ void split_one(float a, __nv_bfloat16 &hi, __nv_bfloat16 &lo) {
    hi = __float2bfloat16(a);
    lo = __float2bfloat16(a - __bfloat162float(hi));
}
__device__ __forceinline__ void split_pair(float a, float b, unsigned &hi, unsigned &lo) {
    __nv_bfloat16 ah, al, bh, bl;
    split_one(a, ah, al);
    split_one(b, bh, bl);
    hi = ((unsigned)__bfloat16_as_ushort(bh) << 16) | (unsigned)__bfloat16_as_ushort(ah);
    lo = ((unsigned)__bfloat16_as_ushort(bl) << 16) | (unsigned)__bfloat16_as_ushort(al);
}
#define CP_ASYNC16(dst, src) \
    asm volatile("cp.async.cg.shared.global [%0], [%1], 16;" :: "r"(dst), "l"(src))
#define CP_COMMIT()  asm volatile("cp.async.commit_group;")
#define CP_WAIT1()   asm volatile("cp.async.wait_group 1;")
#define CP_WAIT0()   asm volatile("cp.async.wait_group 0;")

// ---------------- K0: zero accumulators ----------------
__global__ void k_zero() {
    int i = blockIdx.x * blockDim.x + threadIdx.x;
    if (i < B_*H_*G_*D_) g_st[i] = 0.f;
    if (i < B_*H_*G_)    g_nrm[i] = 0.f;
}

// ---------------- K_sx: split x into bf16 hi/lo ----------------
__global__ void __launch_bounds__(256) k_split_x(const float* __restrict__ x) {
    size_t i = (size_t)blockIdx.x * 256 + threadIdx.x;
    float4 v = *(const float4*)(x + i * 4);
    unsigned h0, l0, h1, l1;
    split_pair(v.x, v.y, h0, l0);
    split_pair(v.z, v.w, h1, l1);
    *(uint2*)&g_xhi[i * 4] = make_uint2(h0, h1);
    *(uint2*)&g_xlo[i * 4] = make_uint2(l0, l1);
}

// ---------------- K_sw: split + transpose W_fx|W_x, build bias ----------------
__global__ void __launch_bounds__(256) k_split_W(
    const float* __restrict__ Wfx, const float* __restrict__ Wx,
    const float* __restrict__ bfx, const float* __restrict__ bx)
{
    int idx = blockIdx.x * 256 + threadIdx.x;
    int n = idx & 1023;
    int k = idx >> 10;
    float v = (n < 512) ? Wfx[k * 512 + n] : Wx[k * 512 + (n - 512)];
    __nv_bfloat16 hi, lo;
    split_one(v, hi, lo);
    g_Whi[n * 256 + k] = hi;
    g_Wlo[n * 256 + k] = lo;
    if (blockIdx.x == 0) {
        for (int j = threadIdx.x; j < 1024; j += 256)
            g_bias0[j] = (j < 512) ? bfx[j] : bx[j - 512];
    }
}

// ================= split-bf16 tensor-core GEMM, cp.async pipelined =================
// mode 0: fx tiles (n0<512): 3 passes, write g_fxhi/g_fxlo (bf16 split)
//         xm tiles (n0>=512): 1 pass, write g_xmhi (bf16)
// mode 1: 3 passes, write fp32 OutF (final output)

#define GK_ROWB 80                      // 32 halves + 8 pad = 80B (16B-aligned rows!)
#define GK_ARR  (128 * GK_ROWB)         // 10240
#define GK_STG  (4 * GK_ARR)            // 40960 per stage
#define GK_SMEM (2 * GK_STG)            // 81920

__global__ void __launch_bounds__(256, 2) k_gemm_ts(
    const __nv_bfloat16* __restrict__ Ahi, const __nv_bfloat16* __restrict__ Alo,
    const __nv_bfloat16* __restrict__ Bhi, const __nv_bfloat16* __restrict__ Blo,
    int K, int mode,
    const float* __restrict__ bias,
    float* __restrict__ OutF, int ldc)
{
    char* sm = smem_dyn;
    const uint32_t sbase = smem_to_u32(sm);

    const int tid  = threadIdx.x;
    const int wid  = tid >> 5;
    const int lane = tid & 31;
    const int wm   = wid >> 2;
    const int wn   = wid & 3;
    const int m0   = blockIdx.y * 128;
    const int n0   = blockIdx.x * 128;
    const int npass = (mode == 0 && n0 >= 512) ? 1 : 3;

    const __nv_bfloat16* srcs[4];
    srcs[0] = Ahi + (size_t)m0 * K;
    srcs[1] = Alo + (size_t)m0 * K;
    size_t boff = (size_t)(mode ? (m0 >> 15) : 0) * 256 * INNER_ + (size_t)n0 * K;
    srcs[2] = Bhi + boff;
    srcs[3] = Blo + boff;

    const int srow0 = tid >> 2,         sq0 = tid & 3;
    const int srow1 = (tid + 256) >> 2, sq1 = (tid + 256) & 3;

    float acc[4][4][4];
#pragma unroll
    for (int i = 0; i < 4; i++)
#pragma unroll
        for (int j = 0; j < 4; j++)
#pragma unroll
            for (int e = 0; e < 4; e++) acc[i][j][e] = 0.f;

    const int lrow = lane & 15;
    const int lkq  = (lane >> 4) << 3;
    const int nch  = K >> 5;

    // prologue: stage chunk 0 into stage 0
#pragma unroll
    for (int arr = 0; arr < 4; arr++) {
        if (npass == 1 && (arr & 1)) continue;      // skip lo arrays
        const __nv_bfloat16* s = srcs[arr];
        uint32_t d = sbase + arr * GK_ARR;
        CP_ASYNC16(d + srow0 * GK_ROWB + sq0 * 16, s + (size_t)srow0 * K + sq0 * 8);
        CP_ASYNC16(d + srow1 * GK_ROWB + sq1 * 16, s + (size_t)srow1 * K + sq1 * 8);
    }
    CP_COMMIT();

    for (int ch = 0; ch < nch; ch++) {
        if (ch + 1 < nch) {
            const int k1 = (ch + 1) << 5;
            const uint32_t stg = sbase + ((ch + 1) & 1) * GK_STG;
#pragma unroll
            for (int arr = 0; arr < 4; arr++) {
                if (npass == 1 && (arr & 1)) continue;
                const __nv_bfloat16* s = srcs[arr] + k1;
                uint32_t d = stg + arr * GK_ARR;
                CP_ASYNC16(d + srow0 * GK_ROWB + sq0 * 16, s + (size_t)srow0 * K + sq0 * 8);
                CP_ASYNC16(d + srow1 * GK_ROWB + sq1 * 16, s + (size_t)srow1 * K + sq1 * 8);
            }
            CP_COMMIT();
            CP_WAIT1();
        } else {
            CP_WAIT0();
        }
        __syncthreads();

        const uint32_t stg  = sbase + (ch & 1) * GK_STG;
        const uint32_t sahi = stg, salo = stg + GK_ARR;
        const uint32_t sbhi = stg + 2 * GK_ARR, sblo = stg + 3 * GK_ARR;

#pragma unroll
        for (int ks = 0; ks < 2; ks++) {
            const int khb = (ks * 16 + lkq) * 2;
            uint32_t a[4][4], bh[8], bl[8];
#pragma unroll
            for (int i = 0; i < 4; i++) {
                int row = wm * 64 + i * 16 + lrow;
                ldsm4(a[i][0], a[i][1], a[i][2], a[i][3], sahi + row * GK_ROWB + khb);
            }
#pragma unroll
            for (int jp = 0; jp < 2; jp++) {
                int row = wn * 32 + jp * 16 + lrow;
                ldsm4(bh[jp*4+0], bh[jp*4+1], bh[jp*4+2], bh[jp*4+3],
                      sbhi + row * GK_ROWB + khb);
            }
#pragma unroll
            for (int i = 0; i < 4; i++) {           // hh
                mma16816(acc[i][0], a[i][0], a[i][1], a[i][2], a[i][3], bh[0], bh[2]);
                mma16816(acc[i][1], a[i][0], a[i][1], a[i][2], a[i][3], bh[1], bh[3]);
                mma16816(acc[i][2], a[i][0], a[i][1], a[i][2], a[i][3], bh[4], bh[6]);
                mma16816(acc[i][3], a[i][0], a[i][1], a[i][2], a[i][3], bh[5], bh[7]);
            }
            if (npass == 3) {
#pragma unroll
                for (int jp = 0; jp < 2; jp++) {
                    int row = wn * 32 + jp * 16 + lrow;
                    ldsm4(bl[jp*4+0], bl[jp*4+1], bl[jp*4+2], bl[jp*4+3],
                          sblo + row * GK_ROWB + khb);
                }
#pragma unroll
                for (int i = 0; i < 4; i++) {       // hl
                    mma16816(acc[i][0], a[i][0], a[i][1], a[i][2], a[i][3], bl[0], bl[2]);
                    mma16816(acc[i][1], a[i][0], a[i][1], a[i][2], a[i][3], bl[1], bl[3]);
                    mma16816(acc[i][2], a[i][0], a[i][1], a[i][2], a[i][3], bl[4], bl[6]);
                    mma16816(acc[i][3], a[i][0], a[i][1], a[i][2], a[i][3], bl[5], bl[7]);
                }
#pragma unroll
                for (int i = 0; i < 4; i++) {
                    int row = wm * 64 + i * 16 + lrow;
                    ldsm4(a[i][0], a[i][1], a[i][2], a[i][3], salo + row * GK_ROWB + khb);
                }
#pragma unroll
                for (int i = 0; i < 4; i++) {       // lh
                    mma16816(acc[i][0], a[i][0], a[i][1], a[i][2], a[i][3], bh[0], bh[2]);
                    mma16816(acc[i][1], a[i][0], a[i][1], a[i][2], a[i][3], bh[1], bh[3]);
                    mma16816(acc[i][2], a[i][0], a[i][1], a[i][2], a[i][3], bh[4], bh[6]);
                    mma16816(acc[i][3], a[i][0], a[i][1], a[i][2], a[i][3], bh[5], bh[7]);
                }
            }
        }
        __syncthreads();
    }

    // ---- epilogue ----
    const int r0 = lane >> 2;
    const int c0 = (lane & 3) * 2;
    if (mode == 1) {
#pragma unroll
        for (int j = 0; j < 4; j++) {
            const int col = n0 + wn * 32 + j * 8 + c0;
            const float2 bi = *(const float2*)&bias[col];
#pragma unroll
            for (int i = 0; i < 4; i++) {
                const int row = m0 + wm * 64 + i * 16 + r0;
                float2 o0 = {acc[i][j][0] + bi.x, acc[i][j][1] + bi.y};
                float2 o1 = {acc[i][j][2] + bi.x, acc[i][j][3] + bi.y};
                *(float2*)&OutF[(size_t)row * ldc + col] = o0;
                *(float2*)&OutF[(size_t)(row + 8) * ldc + col] = o1;
            }
        }
    } else {
        const bool isfx = (n0 < 512);
        const int nbase = isfx ? n0 : (n0 - 512);
#pragma unroll
        for (int j = 0; j < 4; j++) {
            const int colA = n0 + wn * 32 + j * 8 + c0;
            const int colL = nbase + wn * 32 + j * 8 + c0;
            const float2 bi = *(const float2*)&bias[colA];
#pragma unroll
            for (int i = 0; i < 4; i++) {
                const int row = m0 + wm * 64 + i * 16 + r0;
                unsigned h0, l0, h1, l1;
                split_pair(acc[i][j][0] + bi.x, acc[i][j][1] + bi.y, h0, l0);
                split_pair(acc[i][j][2] + bi.x, acc[i][j][3] + bi.y, h1, l1);
                if (isfx) {
                    *(unsigned*)&g_fxhi[(size_t)row * 512 + colL]       = h0;
                    *(unsigned*)&g_fxlo[(size_t)row * 512 + colL]       = l0;
                    *(unsigned*)&g_fxhi[(size_t)(row + 8) * 512 + colL] = h1;
                    *(unsigned*)&g_fxlo[(size_t)(row + 8) * 512 + colL] = l1;
                } else {
                    *(unsigned*)&g_xmhi[(size_t)row * 512 + colL]       = h0;
                    *(unsigned*)&g_xmhi[(size_t)(row + 8) * 512 + colL] = h1;
                }
            }
        }
    }
}

// ================= K_B: tensorized fused logits+softmax+pooling =================
// Phase 1 (single pass): L = xm_hi @ Ws_hi^T -> softmax -> w
// Phase 2 (3 pass): st = w^T @ fx -> atomicAdd partials

#define TOK 256
#define PXMH 0                           // [256][144B] xm_hi, then fx_hi
#define PXML 36864                       // [256][144B] fx_lo (prefetched)
#define PWS  73728                       // [64][144B]  Ws^T hi
#define PWTH 82944                       // [64][528B]  w^T hi
#define PWTL 116736                      // [64][528B]  w^T lo
#define PBSL 150528
#define PNRM 150784
#define SMEM_POOL 151808

__global__ void __launch_bounds__(256) k_pool(
    const float* __restrict__ Wslice, const float* __restrict__ bslice,
    const float* __restrict__ temperature)
{
    char* sm = smem_dyn;
    const uint32_t sbase = smem_to_u32(sm);
    float* bslf = (float*)(sm + PBSL);
    float* nrmp = (float*)(sm + PNRM);

    const int h  = blockIdx.x;
    const int tb = blockIdx.y;
    const int b  = blockIdx.z;
    const int tid = threadIdx.x;
    const int wid = tid >> 5;
    const int lane = tid & 31;
    const int m0  = b * N_ + tb * TOK;
    const int lrow = lane & 15;
    const int lkq  = (lane >> 4) << 3;

    // prefetch xm_hi (phase 1) and fx_lo (phase 2) via cp.async
#pragma unroll
    for (int it = 0; it < 8; it++) {
        int i = tid + it * 256;          // 0..2047
        int r = i >> 3, q = i & 7;
        CP_ASYNC16(sbase + PXMH + r*144 + q*16,
                   &g_xmhi[(size_t)(m0+r)*512 + h*64 + q*8]);
        CP_ASYNC16(sbase + PXML + r*144 + q*16,
                   &g_fxlo[(size_t)(m0+r)*512 + h*64 + q*8]);
    }
    CP_COMMIT();

    // stage Ws^T hi
#pragma unroll
    for (int it = 0; it < 16; it++) {
        int i = tid + it * 256;
        int d = i >> 6, g = i & 63;
        *(__nv_bfloat16*)(sm + PWS + g*144 + d*2) = __float2bfloat16(Wslice[d*64 + g]);
    }
    if (tid < 64) bslf[tid] = bslice[tid];
    CP_WAIT0();
    __syncthreads();

    // ---- phase 1 MMA (single pass): 256x64x64, warp tile 32x64 ----
    float acc[2][8][4];
#pragma unroll
    for (int i = 0; i < 2; i++)
#pragma unroll
        for (int j = 0; j < 8; j++)
#pragma unroll
            for (int e = 0; e < 4; e++) acc[i][j][e] = 0.f;

#pragma unroll
    for (int ks = 0; ks < 4; ks++) {
        const int khb = (ks * 16 + lkq) * 2;
        uint32_t a[2][4], bh[16];
#pragma unroll
        for (int i = 0; i < 2; i++) {
            int row = wid * 32 + i * 16 + lrow;
            ldsm4(a[i][0], a[i][1], a[i][2], a[i][3], sbase + PXMH + row*144 + khb);
        }
#pragma unroll
        for (int jp = 0; jp < 4; jp++) {
            int row = jp * 16 + lrow;
            ldsm4(bh[jp*4+0], bh[jp*4+1], bh[jp*4+2], bh[jp*4+3],
                  sbase + PWS + row*144 + khb);
        }
#pragma unroll
        for (int i = 0; i < 2; i++)
#pragma unroll
            for (int jj = 0; jj < 8; jj++) {
                int jp = jj >> 1, o = jj & 1;
                mma16816(acc[i][jj], a[i][0], a[i][1], a[i][2], a[i][3],
                         bh[jp*4+o], bh[jp*4+o+2]);
            }
    }

    // ---- softmax over g (in registers, quad shuffles) ----
    float tmp = temperature[h];
    tmp = fminf(fmaxf(tmp, 0.1f), 5.0f);
    const float itemp = 1.0f / tmp;

#pragma unroll
    for (int i = 0; i < 2; i++)
#pragma unroll
        for (int j = 0; j < 8; j++) {
            float2 bi = *(float2*)&bslf[j*8 + (lane & 3)*2];
            acc[i][j][0] = (acc[i][j][0] + bi.x) * itemp;
            acc[i][j][1] = (acc[i][j][1] + bi.y) * itemp;
            acc[i][j][2] = (acc[i][j][2] + bi.x) * itemp;
            acc[i][j][3] = (acc[i][j][3] + bi.y) * itemp;
        }
    float inv0[2], inv1[2];
#pragma unroll
    for (int i = 0; i < 2; i++) {
        float m0v = -1e30f, m1v = -1e30f;
#pragma unroll
        for (int j = 0; j < 8; j++) {
            m0v = fmaxf(m0v, fmaxf(acc[i][j][0], acc[i][j][1]));
            m1v = fmaxf(m1v, fmaxf(acc[i][j][2], acc[i][j][3]));
        }
        m0v = fmaxf(m0v, __shfl_xor_sync(0xffffffff, m0v, 1));
        m0v = fmaxf(m0v, __shfl_xor_sync(0xffffffff, m0v, 2));
        m1v = fmaxf(m1v, __shfl_xor_sync(0xffffffff, m1v, 1));
        m1v = fmaxf(m1v, __shfl_xor_sync(0xffffffff, m1v, 2));
        float s0 = 0.f, s1 = 0.f;
#pragma unroll
        for (int j = 0; j < 8; j++) {
            acc[i][j][0] = __expf(acc[i][j][0] - m0v);
            acc[i][j][1] = __expf(acc[i][j][1] - m0v);
            acc[i][j][2] = __expf(acc[i][j][2] - m1v);
            acc[i][j][3] = __expf(acc[i][j][3] - m1v);
            s0 += acc[i][j][0] + acc[i][j][1];
            s1 += acc[i][j][2] + acc[i][j][3];
        }
        s0 += __shfl_xor_sync(0xffffffff, s0, 1);
        s0 += __shfl_xor_sync(0xffffffff, s0, 2);
        s1 += __shfl_xor_sync(0xffffffff, s1, 1);
        s1 += __shfl_xor_sync(0xffffffff, s1, 2);
        inv0[i] = 1.0f / s0;
        inv1[i] = 1.0f / s1;
    }

    // ---- write w: to WT smem (split, [g][t]) and to g_w gmem (split) ----
    {
        const int r = lane >> 2;
#pragma unroll
        for (int i = 0; i < 2; i++) {
            int t0 = wid * 32 + i * 16 + r;
            int t1 = t0 + 8;
#pragma unroll
            for (int j = 0; j < 8; j++) {
                int c = j * 8 + (lane & 3) * 2;
                float w00 = acc[i][j][0] * inv0[i], w01 = acc[i][j][1] * inv0[i];
                float w10 = acc[i][j][2] * inv1[i], w11 = acc[i][j][3] * inv1[i];
                unsigned h0, l0, h1, l1;
                split_pair(w00, w01, h0, l0);
                split_pair(w10, w11, h1, l1);
                *(unsigned*)&g_whi[(size_t)(m0 + t0)*512 + h*64 + c] = h0;
                *(unsigned*)&g_wlo[(size_t)(m0 + t0)*512 + h*64 + c] = l0;
                *(unsigned*)&g_whi[(size_t)(m0 + t1)*512 + h*64 + c] = h1;
                *(unsigned*)&g_wlo[(size_t)(m0 + t1)*512 + h*64 + c] = l1;
                *(__nv_bfloat16*)(sm + PWTH + c*528 + t0*2)     = __ushort_as_bfloat16((unsigned short)(h0 & 0xffff));
                *(__nv_bfloat16*)(sm + PWTH + (c+1)*528 + t0*2) = __ushort_as_bfloat16((unsigned short)(h0 >> 16));
                *(__nv_bfloat16*)(sm + PWTL + c*528 + t0*2)     = __ushort_as_bfloat16((unsigned short)(l0 & 0xffff));
                *(__nv_bfloat16*)(sm + PWTL + (c+1)*528 + t0*2) = __ushort_as_bfloat16((unsigned short)(l0 >> 16));
                *(__nv_bfloat16*)(sm + PWTH + c*528 + t1*2)     = __ushort_as_bfloat16((unsigned short)(h1 & 0xffff));
                *(__nv_bfloat16*)(sm + PWTH + (c+1)*528 + t1*2) = __ushort_as_bfloat16((unsigned short)(h1 >> 16));
                *(__nv_bfloat16*)(sm + PWTL + c*528 + t1*2)     = __ushort_as_bfloat16((unsigned short)(l1 & 0xffff));
                *(__nv_bfloat16*)(sm + PWTL + (c+1)*528 + t1*2) = __ushort_as_bfloat16((unsigned short)(l1 >> 16));
            }
        }
    }
    __syncthreads();   // phase-1 reads of PXMH done; w visible in PWT

    // prefetch fx_hi into PXMH (overlaps norm computation)
#pragma unroll
    for (int it = 0; it < 8; it++) {
        int i = tid + it * 256;
        int r = i >> 3, q = i & 7;
        CP_ASYNC16(sbase + PXMH + r*144 + q*16,
                   &g_fxhi[(size_t)(m0+r)*512 + h*64 + q*8]);
    }
    CP_COMMIT();

    // ---- norm partial sums (w^T row sums) ----
    {
        int g = tid & 63, q = tid >> 6;
        float s = 0.f;
        const __nv_bfloat16* ph = (const __nv_bfloat16*)(sm + PWTH + g*528);
        const __nv_bfloat16* pl = (const __nv_bfloat16*)(sm + PWTL + g*528);
#pragma unroll 8
        for (int t = q*64; t < q*64 + 64; t++)
            s += __bfloat162float(ph[t]) + __bfloat162float(pl[t]);
        nrmp[q*64 + g] = s;
    }
    __syncthreads();
    if (tid < 64) {
        float s = nrmp[tid] + nrmp[64+tid] + nrmp[128+tid] + nrmp[192+tid];
        atomicAdd(&g_nrm[(b*8 + h)*64 + tid], s);
    }
    CP_WAIT0();
    __syncthreads();

    // ---- phase 2 MMA: st[64x64] = w^T @ fx, K=256; warp tile 32x16 ----
    const int wm2 = wid >> 2;
    const int wn2 = wid & 3;
    float ac2[2][2][4];
#pragma unroll
    for (int i = 0; i < 2; i++)
#pragma unroll
        for (int j = 0; j < 2; j++)
#pragma unroll
            for (int e = 0; e < 4; e++) ac2[i][j][e] = 0.f;

#pragma unroll
    for (int ks = 0; ks < 16; ks++) {
        const int khb = (ks * 16 + lkq) * 2;
        uint32_t a[2][4], bhv[4], blv[4];
#pragma unroll
        for (int i = 0; i < 2; i++) {
            int row = wm2 * 32 + i * 16 + lrow;
            ldsm4(a[i][0], a[i][1], a[i][2], a[i][3], sbase + PWTH + row*528 + khb);
        }
        {
            int trow = ks * 16 + lrow;
            uint32_t addr = sbase + PXMH + trow*144 + (wn2*16 + lkq)*2;
            ldsm4t(bhv[0], bhv[1], bhv[2], bhv[3], addr);
        }
#pragma unroll
        for (int i = 0; i < 2; i++) {
            mma16816(ac2[i][0], a[i][0], a[i][1], a[i][2], a[i][3], bhv[0], bhv[1]);
            mma16816(ac2[i][1], a[i][0], a[i][1], a[i][2], a[i][3], bhv[2], bhv[3]);
        }
        {
            int trow = ks * 16 + lrow;
            uint32_t addr = sbase + PXML + trow*144 + (wn2*16 + lkq)*2;
            ldsm4t(blv[0], blv[1], blv[2], blv[3], addr);
        }
#pragma unroll
        for (int i = 0; i < 2; i++) {
            mma16816(ac2[i][0], a[i][0], a[i][1], a[i][2], a[i][3], blv[0], blv[1]);
            mma16816(ac2[i][1], a[i][0], a[i][1], a[i][2], a[i][3], blv[2], blv[3]);
        }
#pragma unroll
        for (int i = 0; i < 2; i++) {
            int row = wm2 * 32 + i * 16 + lrow;
            ldsm4(a[i][0], a[i][1], a[i][2], a[i][3], sbase + PWTL + row*528 + khb);
        }
#pragma unroll
        for (int i = 0; i < 2; i++) {
            mma16816(ac2[i][0], a[i][0], a[i][1], a[i][2], a[i][3], bhv[0], bhv[1]);
            mma16816(ac2[i][1], a[i][0], a[i][1], a[i][2], a[i][3], bhv[2], bhv[3]);
        }
    }

    // ---- atomic partial reduction into g_st ----
    {
        const int base = (b*8 + h) * 64;
        const int r = lane >> 2;
        const int cq = (lane & 3) * 2;
#pragma unroll
        for (int i = 0; i < 2; i++) {
            int g0r = wm2 * 32 + i * 16 + r;
#pragma unroll
            for (int jj = 0; jj < 2; jj++) {
                int d = wn2 * 16 + jj * 8 + cq;
                atomicAdd(&g_st[(base + g0r)*64 + d],     ac2[i][jj][0]);
                atomicAdd(&g_st[(base + g0r)*64 + d + 1], ac2[i][jj][1]);
                atomicAdd(&g_st[(base + g0r + 8)*64 + d],     ac2[i][jj][2]);
                atomicAdd(&g_st[(base + g0r + 8)*64 + d + 1], ac2[i][jj][3]);
            }
        }
    }
}

// ---------------- K_C1: tiny attention over slice tokens (256 thr) ----------------
#define SMEM_ATTN (5*64*65*4)            // 83200
__global__ void __launch_bounds__(256) k_attn(
    const float* __restrict__ Wq, const float* __restrict__ Wk,
    const float* __restrict__ Wv)
{
    float* sm = (float*)smem_dyn;
    float* S  = sm;
    float* Qs = sm + 64*65;
    float* Ks = sm + 2*64*65;
    float* Vs = sm + 3*64*65;
    float* Ps = sm + 4*64*65;

    const int h = blockIdx.x, b = blockIdx.y;
    const int tid = threadIdx.x;
    const int base = (b*8 + h) * 64;
    const int g  = tid >> 2;
    const int qd = (tid & 3) * 16;

    {
        float invn = 1.0f / (g_nrm[base + g] + 1e-5f);
#pragma unroll
        for (int j = 0; j < 16; j += 4) {
            float4 v = *(const float4*)&g_st[(base + g)*64 + qd + j];
            S[g*65 + qd + j]   = v.x * invn;
            S[g*65 + qd + j+1] = v.y * invn;
            S[g*65 + qd + j+2] = v.z * invn;
            S[g*65 + qd + j+3] = v.w * invn;
        }
    }
    __syncthreads();

    {
        float aq[16], ak[16], av[16];
#pragma unroll
        for (int j = 0; j < 16; j++) { aq[j] = 0.f; ak[j] = 0.f; av[j] = 0.f; }
        for (int k = 0; k < 64; k++) {
            float sv = S[g*65 + k];
            const float* wq = &Wq[k*64 + qd];
            const float* wk = &Wk[k*64 + qd];
            const float* wv = &Wv[k*64 + qd];
#pragma unroll
            for (int j = 0; j < 16; j++) {
                aq[j] += sv * wq[j];
                ak[j] += sv * wk[j];
                av[j] += sv * wv[j];
            }
        }
#pragma unroll
        for (int j = 0; j < 16; j++) {
            Qs[g*65 + qd + j] = aq[j];
            Ks[g*65 + qd + j] = ak[j];
            Vs[g*65 + qd + j] = av[j];
        }
    }
    __syncthreads();

    {
        float lg[16];
#pragma unroll
        for (int jj = 0; jj < 16; jj++) {
            int j = qd + jj;
            float dot = 0.f;
#pragma unroll
            for (int d = 0; d < 64; d++) dot += Qs[g*65 + d] * Ks[j*65 + d];
            lg[jj] = dot * 0.125f;
        }
        float mx = -1e30f;
#pragma unroll
        for (int jj = 0; jj < 16; jj++) mx = fmaxf(mx, lg[jj]);
        mx = fmaxf(mx, __shfl_xor_sync(0xffffffff, mx, 1));
        mx = fmaxf(mx, __shfl_xor_sync(0xffffffff, mx, 2));
        float s = 0.f;
#pragma unroll
        for (int jj = 0; jj < 16; jj++) { lg[jj] = __expf(lg[jj] - mx); s += lg[jj]; }
        s += __shfl_xor_sync(0xffffffff, s, 1);
        s += __shfl_xor_sync(0xffffffff, s, 2);
        float inv = 1.0f / s;
#pragma unroll
        for (int jj = 0; jj < 16; jj++) Ps[g*65 + qd + jj] = lg[jj] * inv;
    }
    __syncthreads();

    {
        float o[16];
#pragma unroll
        for (int d = 0; d < 16; d++) o[d] = 0.f;
        for (int j = 0; j < 64; j++) {
            float p = Ps[g*65 + j];
#pragma unroll
            for (int d = 0; d < 16; d++) o[d] += p * Vs[j*65 + qd + d];
        }
#pragma unroll
        for (int d = 0; d < 16; d++)
            g_os[(base + g)*64 + qd + d] = o[d];
    }
}

// ---------------- K_C2: P_t[b][c][h*64+g] split bf16 ----------------
#define SMEM_P ((64*68 + 64*256) * (int)sizeof(float))
__global__ void __launch_bounds__(256) k_P(const float* __restrict__ Wout)
{
    float* sm = (float*)smem_dyn;
    float* Os  = sm;
    float* Wsm = sm + 64*68;

    const int h = blockIdx.x, b = blockIdx.y;
    const int tid = threadIdx.x;
    const int base = (b*8 + h) * 64;

    for (int i = tid; i < 64*16; i += 256) {
        int r = i >> 4, c = i & 15;
        *(float4*)&Os[r*68 + c*4] = *(const float4*)&g_os[(size_t)(base + r)*64 + c*4];
    }
    for (int i = tid; i < 64*64; i += 256) {
        int r = i >> 6, c = i & 63;
        *(float4*)&Wsm[r*256 + c*4] = *(const float4*)&Wout[(size_t)(h*64 + r)*256 + c*4];
    }
    __syncthreads();

    const int gq = tid >> 3;
    const int cq = tid & 7;
    const int g0 = gq * 2;
    const int c0 = cq * 32;

    float acc[2][32];
#pragma unroll
    for (int i = 0; i < 2; i++)
#pragma unroll
        for (int j = 0; j < 32; j++) acc[i][j] = 0.f;

    for (int k = 0; k < 64; k++) {
        float a0 = Os[(g0+0)*68 + k];
        float a1 = Os[(g0+1)*68 + k];
#pragma unroll
        for (int c4 = 0; c4 < 8; c4++) {
            float4 w = *(float4*)&Wsm[k*256 + c0 + c4*4];
            acc[0][c4*4+0] += a0*w.x; acc[0][c4*4+1] += a0*w.y;
            acc[0][c4*4+2] += a0*w.z; acc[0][c4*4+3] += a0*w.w;
            acc[1][c4*4+0] += a1*w.x; acc[1][c4*4+1] += a1*w.y;
            acc[1][c4*4+2] += a1*w.z; acc[1][c4*4+3] += a1*w.w;
        }
    }
    __nv_bfloat16* Ph = &g_Pthi[(size_t)b * C_ * INNER_];
    __nv_bfloat16* Pl = &g_Ptlo[(size_t)b * C_ * INNER_];
#pragma unroll
    for (int i = 0; i < 2; i++)
#pragma unroll
        for (int c4 = 0; c4 < 8; c4++)
#pragma unroll
            for (int e = 0; e < 4; e++) {
                size_t off = (size_t)(c0 + c4*4 + e) * INNER_ + h*64 + g0 + i;
                __nv_bfloat16 hi, lo;
                split_one(acc[i][c4*4+e], hi, lo);
                Ph[off] = hi;
                Pl[off] = lo;
            }
}

// ---------------- launch ----------------
extern "C" void kernel_launch(void* const* d_in, const int* in_sizes, int n_in,
                              void* d_out, int out_size)
{
    const float* x    = (const float*)d_in[0];
    const float* Wfx  = (const float*)d_in[1];
    const float* bfx  = (const float*)d_in[2];
    const float* Wx   = (const float*)d_in[3];
    const float* bx   = (const float*)d_in[4];
    const float* Wsl  = (const float*)d_in[5];
    const float* bsl  = (const float*)d_in[6];
    const float* temp = (const float*)d_in[7];
    const float* Wq   = (const float*)d_in[8];
    const float* Wk   = (const float*)d_in[9];
    const float* Wv   = (const float*)d_in[10];
    const float* Wout = (const float*)d_in[11];
    const float* bout = (const float*)d_in[12];
    float* out = (float*)d_out;

    static bool init = false;
    static float *g_bias0_p;
    static __nv_bfloat16 *g_xhi_p, *g_xlo_p, *g_Whi_p, *g_Wlo_p;
    static __nv_bfloat16 *g_whi_p, *g_wlo_p, *g_Pthi_p, *g_Ptlo_p;
    if (!init) {
        cudaGetSymbolAddress((void**)&g_bias0_p, g_bias0);
        cudaGetSymbolAddress((void**)&g_xhi_p,   g_xhi);
        cudaGetSymbolAddress((void**)&g_xlo_p,   g_xlo);
        cudaGetSymbolAddress((void**)&g_Whi_p,   g_Whi);
        cudaGetSymbolAddress((void**)&g_Wlo_p,   g_Wlo);
        cudaGetSymbolAddress((void**)&g_whi_p,   g_whi);
        cudaGetSymbolAddress((void**)&g_wlo_p,   g_wlo);
        cudaGetSymbolAddress((void**)&g_Pthi_p,  g_Pthi);
        cudaGetSymbolAddress((void**)&g_Ptlo_p,  g_Ptlo);
        cudaFuncSetAttribute(k_gemm_ts, cudaFuncAttributeMaxDynamicSharedMemorySize, GK_SMEM);
        cudaFuncSetAttribute(k_pool, cudaFuncAttributeMaxDynamicSharedMemorySize, SMEM_POOL);
        cudaFuncSetAttribute(k_attn, cudaFuncAttributeMaxDynamicSharedMemorySize, SMEM_ATTN);
        cudaFuncSetAttribute(k_P,    cudaFuncAttributeMaxDynamicSharedMemorySize, SMEM_P);
        init = true;
    }

    // 0) zero accumulators + operand splitting
    k_zero<<<(B_*H_*G_*D_ + 255)/256, 256>>>();
    k_split_x<<<(BNTOK * 256 / 4) / 256, 256>>>(x);
    k_split_W<<<262144 / 256, 256>>>(Wfx, Wx, bfx, bx);

    // 1) projections -> split bf16 fx / xm (fx 3-pass, xm 1-pass)
    k_gemm_ts<<<dim3(8, BNTOK/128), 256, GK_SMEM>>>(
        g_xhi_p, g_xlo_p, g_Whi_p, g_Wlo_p, 256, 0, g_bias0_p, nullptr, 0);

    // 2) fused logits/softmax/pooling (tensor cores)
    k_pool<<<dim3(H_, N_/TOK, B_), 256, SMEM_POOL>>>(Wsl, bsl, temp);

    // 3) tiny attention over slice tokens
    k_attn<<<dim3(H_, B_), 256, SMEM_ATTN>>>(Wq, Wk, Wv);

    // 4) P precompute (transposed + split)
    k_P<<<dim3(H_, B_), 256, SMEM_P>>>(Wout);

    // 5) output GEMM (tensor cores, 3-pass)
    k_gemm_ts<<<dim3(2, BNTOK/128), 256, GK_SMEM>>>(
        g_whi_p, g_wlo_p, g_Pthi_p, g_Ptlo_p, 512, 1, bout, out, 256);
}